// round 2
// baseline (speedup 1.0000x reference)
#include <cuda_runtime.h>
#include <math.h>

#define HID   128
#define TQ    512
#define TK    512
#define QDIM  1024
#define MAXB  2
#define KTILE 128
#define EPSF  1e-5f

// ---------------- scratch (device globals; no allocation allowed) ----------------
__device__ __align__(16) float g_Qp [MAXB * TQ * HID];    // [b][q][h]
__device__ __align__(16) float g_KpT[MAXB * HID * TK];    // [b][j][k]  (transposed)
__device__ float g_sq [MAXB * TQ], g_sq2[MAXB * TQ];
__device__ float g_sk [MAXB * TK], g_sk2[MAXB * TK];
__device__ __align__(16) float g_W1u[HID * HID], g_W2u[HID * HID], g_W3u[HID * HID];
__device__ __align__(16) float g_W1v[HID * HID], g_W2v[HID * HID], g_W3v[HID * HID];
__device__ float g_Gu[HID], g_Bu[HID], g_Gv[HID], g_Bv[HID];

// ---------------- weight prep: Wi = diag(g_block) * W_block ----------------
__global__ void k_wprep(const float* __restrict__ g,
                        const float* __restrict__ Wu,
                        const float* __restrict__ Wv) {
    int j = blockIdx.x;      // 0..127
    int h = threadIdx.x;     // 0..127
    float g0 = g[j], g1 = g[HID + j], g2 = g[2 * HID + j];
    int i0 = j * HID + h, i1 = (HID + j) * HID + h, i2 = (2 * HID + j) * HID + h;
    g_W1u[i0] = g0 * Wu[i0]; g_W2u[i0] = g1 * Wu[i1]; g_W3u[i0] = g2 * Wu[i2];
    g_W1v[i0] = g0 * Wv[i0]; g_W2v[i0] = g1 * Wv[i1]; g_W3v[i0] = g2 * Wv[i2];
}

// Gu[h] = sum_c g_c Wu[c,h] ; Bu[h] = sum_c b_c Wu[c,h] + bu[h]  (same for v)
__global__ void k_gb(const float* __restrict__ g, const float* __restrict__ bln,
                     const float* __restrict__ Wu, const float* __restrict__ bu,
                     const float* __restrict__ Wv, const float* __restrict__ bv) {
    int h = threadIdx.x;
    float Gu = 0.f, Bu = 0.f, Gv = 0.f, Bv = 0.f;
    for (int c = 0; c < 3 * HID; c++) {
        float wu = Wu[c * HID + h], wv = Wv[c * HID + h];
        float gc = g[c], bc = bln[c];
        Gu = fmaf(gc, wu, Gu); Bu = fmaf(bc, wu, Bu);
        Gv = fmaf(gc, wv, Gv); Bv = fmaf(bc, wv, Bv);
    }
    g_Gu[h] = Gu; g_Bu[h] = Bu + bu[h];
    g_Gv[h] = Gv; g_Bv[h] = Bv + bv[h];
}

// ---------------- projection: Qp = Q@Wq (row-major), KpT = (K@Wk)^T ----------------
#define PROJ_ROWS 16
#define PROJ_DCHUNK 256
__global__ __launch_bounds__(128) void k_proj(const float* __restrict__ Q,
                                              const float* __restrict__ K,
                                              const float* __restrict__ Wq,
                                              const float* __restrict__ Wk,
                                              int B) {
    __shared__ __align__(16) float s[PROJ_ROWS][PROJ_DCHUNK];
    int nQ = B * TQ / PROJ_ROWS;
    bool isK = (int)blockIdx.x >= nQ;
    int blk = isK ? (blockIdx.x - nQ) : blockIdx.x;
    const float* X = isK ? K : Q;
    const float* W = isK ? Wk : Wq;
    int row0 = blk * PROJ_ROWS;
    int h = threadIdx.x;

    float acc[PROJ_ROWS];
#pragma unroll
    for (int r = 0; r < PROJ_ROWS; r++) acc[r] = 0.f;

    for (int d0 = 0; d0 < QDIM; d0 += PROJ_DCHUNK) {
        for (int i = threadIdx.x; i < PROJ_ROWS * (PROJ_DCHUNK / 4); i += 128) {
            int r  = i / (PROJ_DCHUNK / 4);
            int c4 = i % (PROJ_DCHUNK / 4);
            float4 v = *(const float4*)&X[(size_t)(row0 + r) * QDIM + d0 + c4 * 4];
            *(float4*)&s[r][c4 * 4] = v;
        }
        __syncthreads();
        for (int dd = 0; dd < PROJ_DCHUNK; dd += 4) {
            float w0 = W[(d0 + dd + 0) * HID + h];
            float w1 = W[(d0 + dd + 1) * HID + h];
            float w2 = W[(d0 + dd + 2) * HID + h];
            float w3 = W[(d0 + dd + 3) * HID + h];
#pragma unroll
            for (int r = 0; r < PROJ_ROWS; r++) {
                float4 sv = *(const float4*)&s[r][dd];
                acc[r] = fmaf(sv.x, w0, acc[r]);
                acc[r] = fmaf(sv.y, w1, acc[r]);
                acc[r] = fmaf(sv.z, w2, acc[r]);
                acc[r] = fmaf(sv.w, w3, acc[r]);
            }
        }
        __syncthreads();
    }
#pragma unroll
    for (int r = 0; r < PROJ_ROWS; r++) {
        int grow = row0 + r;
        if (isK) {
            int b = grow / TK, k = grow % TK;
            g_KpT[((size_t)b * HID + h) * TK + k] = acc[r];
        } else {
            g_Qp[(size_t)grow * HID + h] = acc[r];
        }
    }
}

// ---------------- per-row stats ----------------
__global__ void k_statsq(int B) {
    int warp = blockIdx.x * (blockDim.x >> 5) + (threadIdx.x >> 5);
    int lane = threadIdx.x & 31;
    if (warp >= B * TQ) return;
    float4 v = *(const float4*)&g_Qp[(size_t)warp * HID + lane * 4];
    float s  = v.x + v.y + v.z + v.w;
    float s2 = v.x * v.x + v.y * v.y + v.z * v.z + v.w * v.w;
#pragma unroll
    for (int o = 16; o; o >>= 1) {
        s  += __shfl_down_sync(0xffffffffu, s,  o);
        s2 += __shfl_down_sync(0xffffffffu, s2, o);
    }
    if (lane == 0) { g_sq[warp] = s; g_sq2[warp] = s2; }
}

__global__ void k_statsk(int B) {
    int b = blockIdx.x;
    int k = threadIdx.x;   // 0..511
    float s = 0.f, s2 = 0.f;
#pragma unroll 8
    for (int j = 0; j < HID; j++) {
        float v = g_KpT[((size_t)b * HID + j) * TK + k];
        s += v; s2 = fmaf(v, v, s2);
    }
    g_sk[b * TK + k] = s; g_sk2[b * TK + k] = s2;
}

// ---------------- main fused kernel: one CTA per (b,q) ----------------
struct SmemMain {
    float CmU[HID][HID];   // W2u + diag(q)*W3u
    float CmV[HID][HID];
    float KT [HID][KTILE]; // current K tile, [j][k]
    float qrow[HID], q2row[HID];
    float AqU[HID], AqV[HID];
    float Gu[HID], Bu[HID], Gv[HID], Bv[HID], Wo[HID];
    float rr[KTILE], rmu[KTILE];
};

__global__ __launch_bounds__(512, 1) void k_main(const float* __restrict__ Wo_g,
                                                 const float* __restrict__ bo_g,
                                                 float* __restrict__ out,
                                                 int B) {
    extern __shared__ char smraw[];
    SmemMain& sm = *reinterpret_cast<SmemMain*>(smraw);

    int tid = threadIdx.x;
    int bq  = blockIdx.x;
    int b   = bq / TQ;

    if (tid < HID) {
        float v = g_Qp[(size_t)bq * HID + tid];
        sm.qrow[tid]  = v;
        sm.q2row[tid] = v * v;
        sm.Gu[tid] = g_Gu[tid]; sm.Bu[tid] = g_Bu[tid];
        sm.Gv[tid] = g_Gv[tid]; sm.Bv[tid] = g_Bv[tid];
        sm.Wo[tid] = Wo_g[tid];
    }
    __syncthreads();

    // build Cm matrices (vectorized)
    for (int i = tid; i < HID * HID / 4; i += 512) {
        int j = i / (HID / 4);
        int c = i % (HID / 4);
        float qj = sm.qrow[j];
        float4 w2 = ((const float4*)g_W2u)[i];
        float4 w3 = ((const float4*)g_W3u)[i];
        float4 ou;
        ou.x = fmaf(qj, w3.x, w2.x); ou.y = fmaf(qj, w3.y, w2.y);
        ou.z = fmaf(qj, w3.z, w2.z); ou.w = fmaf(qj, w3.w, w2.w);
        *(float4*)&sm.CmU[j][c * 4] = ou;
        float4 x2 = ((const float4*)g_W2v)[i];
        float4 x3 = ((const float4*)g_W3v)[i];
        float4 ov;
        ov.x = fmaf(qj, x3.x, x2.x); ov.y = fmaf(qj, x3.y, x2.y);
        ov.z = fmaf(qj, x3.z, x2.z); ov.w = fmaf(qj, x3.w, x2.w);
        *(float4*)&sm.CmV[j][c * 4] = ov;
    }
    // Aq_u[h] = sum_j q_j W1u[j,h]   (q-part of LN-folded projection)
    {
        int part = tid >> 7, h = tid & 127;
        if (part == 0) {
            float a = 0.f;
#pragma unroll 8
            for (int j = 0; j < HID; j++) a = fmaf(sm.qrow[j], g_W1u[j * HID + h], a);
            sm.AqU[h] = a;
        } else if (part == 1) {
            float a = 0.f;
#pragma unroll 8
            for (int j = 0; j < HID; j++) a = fmaf(sm.qrow[j], g_W1v[j * HID + h], a);
            sm.AqV[h] = a;
        }
    }
    float sqv  = g_sq[bq];
    float sq2v = g_sq2[bq];
    float bo   = bo_g[0];
    __syncthreads();

    const int hc = tid & 31;     // h-column group (4 h's)
    const int kr = tid >> 5;     // k-row group (8 k's); warp == fixed kr
    const int hbase = hc * 4;
    const int kbase = kr * 8;
    const float inv384 = 1.0f / 384.0f;

    for (int t = 0; t < TK / KTILE; t++) {
        __syncthreads();   // previous tile fully consumed
        // load K tile [j][k]
        for (int i = tid; i < HID * KTILE / 4; i += 512) {
            int j = i >> 5, c = i & 31;
            *(float4*)&sm.KT[j][c * 4] =
                *(const float4*)&g_KpT[((size_t)b * HID + j) * TK + t * KTILE + c * 4];
        }
        __syncthreads();
        // per-k LN stats: mu, var from precomputed row sums + pair dots
        if (tid < KTILE) {
            int k = tid;
            float dqk = 0.f, d22 = 0.f;
#pragma unroll 8
            for (int j = 0; j < HID; j++) {
                float kv = sm.KT[j][k];
                dqk = fmaf(sm.qrow[j], kv, dqk);
                d22 = fmaf(sm.q2row[j], kv * kv, d22);
            }
            int kg = b * TK + t * KTILE + k;
            float mu  = (sqv  + g_sk[kg]  + dqk) * inv384;
            float ms  = (sq2v + g_sk2[kg] + d22) * inv384;
            float var = ms - mu * mu;
            float r   = rsqrtf(var + EPSF);
            sm.rr[k]  = r;
            sm.rmu[k] = r * mu;
        }
        __syncthreads();

        // ---- GEMM: acc[k][h] = Aq[h] + sum_j KT[j][k] * Cm[j][h] ----
        float accU[8][4], accV[8][4];
        {
            float4 au = *(const float4*)&sm.AqU[hbase];
            float4 av = *(const float4*)&sm.AqV[hbase];
#pragma unroll
            for (int i = 0; i < 8; i++) {
                accU[i][0] = au.x; accU[i][1] = au.y; accU[i][2] = au.z; accU[i][3] = au.w;
                accV[i][0] = av.x; accV[i][1] = av.y; accV[i][2] = av.z; accV[i][3] = av.w;
            }
        }
#pragma unroll 2
        for (int j = 0; j < HID; j++) {
            float4 a0 = *(const float4*)&sm.KT[j][kbase];
            float4 a1 = *(const float4*)&sm.KT[j][kbase + 4];
            float4 bu4 = *(const float4*)&sm.CmU[j][hbase];
            float4 bv4 = *(const float4*)&sm.CmV[j][hbase];
            float a[8]  = {a0.x, a0.y, a0.z, a0.w, a1.x, a1.y, a1.z, a1.w};
            float cu[4] = {bu4.x, bu4.y, bu4.z, bu4.w};
            float cv[4] = {bv4.x, bv4.y, bv4.z, bv4.w};
#pragma unroll
            for (int i = 0; i < 8; i++)
#pragma unroll
                for (int c = 0; c < 4; c++) {
                    accU[i][c] = fmaf(a[i], cu[c], accU[i][c]);
                    accV[i][c] = fmaf(a[i], cv[c], accV[i][c]);
                }
        }

        // ---- epilogue: LN fold + gelu + Wo dot + warp reduce over h ----
        float4 gu = *(const float4*)&sm.Gu[hbase];
        float4 bu4 = *(const float4*)&sm.Bu[hbase];
        float4 gv = *(const float4*)&sm.Gv[hbase];
        float4 bv4 = *(const float4*)&sm.Bv[hbase];
        float4 wo = *(const float4*)&sm.Wo[hbase];
        float guA[4] = {gu.x, gu.y, gu.z, gu.w};
        float buA[4] = {bu4.x, bu4.y, bu4.z, bu4.w};
        float gvA[4] = {gv.x, gv.y, gv.z, gv.w};
        float bvA[4] = {bv4.x, bv4.y, bv4.z, bv4.w};
        float woA[4] = {wo.x, wo.y, wo.z, wo.w};

#pragma unroll
        for (int i = 0; i < 8; i++) {
            float R  = sm.rr[kbase + i];
            float RM = sm.rmu[kbase + i];
            float p = 0.f;
#pragma unroll
            for (int c = 0; c < 4; c++) {
                float u = fmaf(R, accU[i][c], fmaf(-RM, guA[c], buA[c]));
                float v = fmaf(R, accV[i][c], fmaf(-RM, gvA[c], bvA[c]));
                float gl = 0.5f * v * (1.0f + erff(v * 0.70710678f));
                p = fmaf(u * gl, woA[c], p);
            }
#pragma unroll
            for (int o = 16; o; o >>= 1) p += __shfl_down_sync(0xffffffffu, p, o);
            if (hc == 0)
                out[(size_t)bq * TK + t * KTILE + kbase + i] = p + bo;
        }
    }
}

// ---------------- launch ----------------
extern "C" void kernel_launch(void* const* d_in, const int* in_sizes, int n_in,
                              void* d_out, int out_size) {
    const float* Q    = (const float*)d_in[0];
    const float* K    = (const float*)d_in[1];
    const float* Wq   = (const float*)d_in[2];
    const float* Wk   = (const float*)d_in[3];
    const float* ln_g = (const float*)d_in[4];
    const float* ln_b = (const float*)d_in[5];
    const float* Wu   = (const float*)d_in[6];
    const float* bu   = (const float*)d_in[7];
    const float* Wv   = (const float*)d_in[8];
    const float* bv   = (const float*)d_in[9];
    const float* Wo   = (const float*)d_in[10];
    const float* bo   = (const float*)d_in[11];

    int B = in_sizes[0] / (TQ * QDIM);
    if (B < 1) B = 1;
    if (B > MAXB) B = MAXB;

    cudaFuncSetAttribute(k_main, cudaFuncAttributeMaxDynamicSharedMemorySize,
                         (int)sizeof(SmemMain));

    k_wprep<<<HID, HID>>>(ln_g, Wu, Wv);
    k_gb<<<1, HID>>>(ln_g, ln_b, Wu, bu, Wv, bv);
    k_proj<<<2 * B * TQ / PROJ_ROWS, 128>>>(Q, K, Wq, Wk, B);
    k_statsq<<<(B * TQ + 7) / 8, 256>>>(B);
    k_statsk<<<B, TK>>>(B);
    k_main<<<B * TQ, 512, sizeof(SmemMain)>>>(Wo, bo, (float*)d_out, B);
}

// round 5
// speedup vs baseline: 2.4877x; 2.4877x over previous
#include <cuda_runtime.h>
#include <cuda_bf16.h>
#include <math.h>
#include <stdint.h>

#define HID   128
#define TQ    512
#define TK    512
#define QDIM  1024
#define MAXB  2
#define EPSF  1e-5f

#define PADJ   136                 // padded row length (bf16 elems) -> 272 B
#define ROWB   (PADJ * 2)          // 272
#define TILEB  (128 * ROWB)        // 34816

// ---------------- device scratch ----------------
__device__ __align__(16) float g_Qp[MAXB * TQ * HID];
__device__ __align__(16) float g_Kp[MAXB * TK * HID];
__device__ __align__(16) float g_W1u[HID * HID], g_W1v[HID * HID];
__device__ __align__(16) float g_W2u[HID * HID], g_W2v[HID * HID];
__device__ __align__(16) __nv_bfloat16 g_W3p[4][128][PADJ];  // [Uh,Ul,Vh,Vl][j][h]
__device__ __align__(16) float g_KW2u[MAXB * TK * HID], g_KW2v[MAXB * TK * HID];
__device__ __align__(16) float g_AqU[MAXB * TQ * HID], g_AqV[MAXB * TQ * HID];
__device__ float g_Gu[HID], g_Bu[HID], g_Gv[HID], g_Bv[HID];

// ---------------- helpers ----------------
__device__ __forceinline__ uint32_t smem_u32(const void* p) {
    uint32_t a;
    asm("{ .reg .u64 t; cvta.to.shared.u64 t, %1; cvt.u32.u64 %0, t; }" : "=r"(a) : "l"(p));
    return a;
}
__device__ __forceinline__ uint32_t b2u(__nv_bfloat162 h) {
    union { __nv_bfloat162 b; uint32_t u; } x; x.b = h; return x.u;
}
#define LDSM_X4(r, a)                                                        \
    asm volatile("ldmatrix.sync.aligned.m8n8.x4.shared.b16 {%0,%1,%2,%3}, [%4];" \
        : "=r"((r)[0]), "=r"((r)[1]), "=r"((r)[2]), "=r"((r)[3]) : "r"(a))
#define LDSM_X2T(r, a)                                                       \
    asm volatile("ldmatrix.sync.aligned.m8n8.x2.trans.shared.b16 {%0,%1}, [%2];" \
        : "=r"((r)[0]), "=r"((r)[1]) : "r"(a))

__device__ __forceinline__ void mma16816(float* d, const uint32_t* a, const uint32_t* b) {
    asm volatile("mma.sync.aligned.m16n8k16.row.col.f32.bf16.bf16.f32 "
        "{%0,%1,%2,%3}, {%4,%5,%6,%7}, {%8,%9}, {%0,%1,%2,%3};"
        : "+f"(d[0]), "+f"(d[1]), "+f"(d[2]), "+f"(d[3])
        : "r"(a[0]), "r"(a[1]), "r"(a[2]), "r"(a[3]), "r"(b[0]), "r"(b[1]));
}

// ---------------- prologue kernels ----------------
__global__ void k_wprep(const float* __restrict__ g,
                        const float* __restrict__ Wu, const float* __restrict__ Wv) {
    int j = blockIdx.x, h = threadIdx.x;
    float g0 = g[j], g1 = g[HID + j], g2 = g[2 * HID + j];
    g_W1u[j * HID + h] = g0 * Wu[j * HID + h];
    g_W1v[j * HID + h] = g0 * Wv[j * HID + h];
    g_W2u[j * HID + h] = g1 * Wu[(HID + j) * HID + h];
    g_W2v[j * HID + h] = g1 * Wv[(HID + j) * HID + h];
    float w3u = g2 * Wu[(2 * HID + j) * HID + h];
    float w3v = g2 * Wv[(2 * HID + j) * HID + h];
    __nv_bfloat16 hu = __float2bfloat16(w3u);
    __nv_bfloat16 hv = __float2bfloat16(w3v);
    g_W3p[0][j][h] = hu;
    g_W3p[1][j][h] = __float2bfloat16(w3u - __bfloat162float(hu));
    g_W3p[2][j][h] = hv;
    g_W3p[3][j][h] = __float2bfloat16(w3v - __bfloat162float(hv));
}

__global__ void k_gb(const float* __restrict__ g, const float* __restrict__ bln,
                     const float* __restrict__ Wu, const float* __restrict__ bu,
                     const float* __restrict__ Wv, const float* __restrict__ bv) {
    int h = threadIdx.x;
    float Gu = 0.f, Bu = 0.f, Gv = 0.f, Bv = 0.f;
    for (int c = 0; c < 3 * HID; c++) {
        float wu = Wu[c * HID + h], wv = Wv[c * HID + h];
        float gc = g[c], bc = bln[c];
        Gu = fmaf(gc, wu, Gu); Bu = fmaf(bc, wu, Bu);
        Gv = fmaf(gc, wv, Gv); Bv = fmaf(bc, wv, Bv);
    }
    g_Gu[h] = Gu; g_Bu[h] = Bu + bu[h];
    g_Gv[h] = Gv; g_Bv[h] = Bv + bv[h];
}

#define PROJ_ROWS 16
#define PROJ_DCHUNK 256
__global__ __launch_bounds__(128) void k_proj(const float* __restrict__ Q,
                                              const float* __restrict__ K,
                                              const float* __restrict__ Wq,
                                              const float* __restrict__ Wk, int B) {
    __shared__ __align__(16) float s[PROJ_ROWS][PROJ_DCHUNK];
    int nQ = B * TQ / PROJ_ROWS;
    bool isK = (int)blockIdx.x >= nQ;
    int blk = isK ? (blockIdx.x - nQ) : blockIdx.x;
    const float* X = isK ? K : Q;
    const float* W = isK ? Wk : Wq;
    int row0 = blk * PROJ_ROWS, h = threadIdx.x;
    float acc[PROJ_ROWS];
#pragma unroll
    for (int r = 0; r < PROJ_ROWS; r++) acc[r] = 0.f;
    for (int d0 = 0; d0 < QDIM; d0 += PROJ_DCHUNK) {
        for (int i = threadIdx.x; i < PROJ_ROWS * (PROJ_DCHUNK / 4); i += 128) {
            int r = i / (PROJ_DCHUNK / 4), c4 = i % (PROJ_DCHUNK / 4);
            *(float4*)&s[r][c4 * 4] = *(const float4*)&X[(size_t)(row0 + r) * QDIM + d0 + c4 * 4];
        }
        __syncthreads();
        for (int dd = 0; dd < PROJ_DCHUNK; dd += 4) {
            float w0 = W[(d0 + dd + 0) * HID + h], w1 = W[(d0 + dd + 1) * HID + h];
            float w2 = W[(d0 + dd + 2) * HID + h], w3 = W[(d0 + dd + 3) * HID + h];
#pragma unroll
            for (int r = 0; r < PROJ_ROWS; r++) {
                float4 sv = *(const float4*)&s[r][dd];
                acc[r] = fmaf(sv.x, w0, acc[r]); acc[r] = fmaf(sv.y, w1, acc[r]);
                acc[r] = fmaf(sv.z, w2, acc[r]); acc[r] = fmaf(sv.w, w3, acc[r]);
            }
        }
        __syncthreads();
    }
#pragma unroll
    for (int r = 0; r < PROJ_ROWS; r++) {
        int grow = row0 + r;
        if (isK) g_Kp[(size_t)grow * HID + h] = acc[r];
        else     g_Qp[(size_t)grow * HID + h] = acc[r];
    }
}

// KW2 = Kp@W2 and Aq = Qp@W1 (u,v each)
__global__ __launch_bounds__(128) void k_lin2(int B) {
    __shared__ __align__(16) float s[16][HID];
    int nK = B * TK / 16;
    bool isQ = (int)blockIdx.x >= nK;
    int blk = isQ ? (blockIdx.x - nK) : blockIdx.x;
    const float* src = isQ ? g_Qp : g_Kp;
    const float* WA  = isQ ? g_W1u : g_W2u;
    const float* WB  = isQ ? g_W1v : g_W2v;
    float* oA = isQ ? g_AqU : g_KW2u;
    float* oB = isQ ? g_AqV : g_KW2v;
    int row0 = blk * 16, h = threadIdx.x;
    for (int i = threadIdx.x; i < 16 * 32; i += 128) {
        int r = i >> 5, c = i & 31;
        *(float4*)&s[r][c * 4] = *(const float4*)&src[(size_t)(row0 + r) * HID + c * 4];
    }
    __syncthreads();
    float au[16], av[16];
#pragma unroll
    for (int r = 0; r < 16; r++) { au[r] = 0.f; av[r] = 0.f; }
    for (int j = 0; j < HID; j++) {
        float wa = WA[j * HID + h], wb = WB[j * HID + h];
#pragma unroll
        for (int r = 0; r < 16; r++) {
            float kv = s[r][j];
            au[r] = fmaf(kv, wa, au[r]); av[r] = fmaf(kv, wb, av[r]);
        }
    }
#pragma unroll
    for (int r = 0; r < 16; r++) {
        oA[(size_t)(row0 + r) * HID + h] = au[r];
        oB[(size_t)(row0 + r) * HID + h] = av[r];
    }
}

// ---------------- main fused kernel ----------------
struct __align__(16) ScalS {
    float qrow[HID];
    float AqU[HID], AqV[HID];
    float Gu[HID], Bu[HID], Gv[HID], Bv[HID], Wo[HID];
    float rr[HID], rmu[HID];
    float pbuf[4][HID];
    float red1[4], red2[4];
    float sq, sq2, bo, pad;
};
#define OFF_BUH 0
#define OFF_BUL (1 * TILEB)
#define OFF_BVH (2 * TILEB)
#define OFF_BVL (3 * TILEB)
#define OFF_AH  (4 * TILEB)
#define OFF_AL  (5 * TILEB)
#define OFF_SCAL (6 * TILEB)
#define SMEM_BYTES (OFF_SCAL + (int)sizeof(ScalS) + 256)

__global__ __launch_bounds__(512, 1) void k_main(const float* __restrict__ Wo_g,
                                                 const float* __restrict__ bo_g,
                                                 float* __restrict__ out) {
    extern __shared__ char smraw[];
    uint32_t sb = smem_u32(smraw);
    uint32_t base = (sb + 127u) & ~127u;
    char* cbase = smraw + (base - sb);
    ScalS* sc = (ScalS*)(cbase + OFF_SCAL);

    const int tid = threadIdx.x;
    const int wrp = tid >> 5, lane = tid & 31;
    const int warpK = wrp & 3, warpH = wrp >> 2;
    const int bq = blockIdx.x, b = bq / TQ;

    // stage B images (W3 u/v hi/lo) into smem
    for (int i = tid; i < 4 * TILEB / 16; i += 512)
        ((uint4*)cbase)[i] = ((const uint4*)g_W3p)[i];
    if (tid < HID) {
        sc->qrow[tid] = g_Qp[(size_t)bq * HID + tid];
        sc->AqU[tid] = g_AqU[(size_t)bq * HID + tid];
        sc->AqV[tid] = g_AqV[(size_t)bq * HID + tid];
        sc->Gu[tid] = g_Gu[tid]; sc->Bu[tid] = g_Bu[tid];
        sc->Gv[tid] = g_Gv[tid]; sc->Bv[tid] = g_Bv[tid];
        sc->Wo[tid] = Wo_g[tid];
    }
    if (tid == 0) sc->bo = bo_g[0];
    __syncthreads();

    if (tid < 128) {
        float q = sc->qrow[tid];
        float s = q, s2 = q * q;
#pragma unroll
        for (int o = 16; o; o >>= 1) {
            s  += __shfl_xor_sync(0xffffffffu, s,  o);
            s2 += __shfl_xor_sync(0xffffffffu, s2, o);
        }
        if (lane == 0) { sc->red1[wrp] = s; sc->red2[wrp] = s2; }
    }
    __syncthreads();
    if (tid == 0) {
        sc->sq  = sc->red1[0] + sc->red1[1] + sc->red1[2] + sc->red1[3];
        sc->sq2 = sc->red2[0] + sc->red2[1] + sc->red2[2] + sc->red2[3];
    }
    __syncthreads();
    const float sqv = sc->sq, sq2v = sc->sq2, inv384 = 1.0f / 384.0f;

    const int k_a = tid >> 2, quad = tid & 3, j0 = quad << 5;
    const uint32_t aAH  = base + OFF_AH,  aAL  = base + OFF_AL;
    const uint32_t aBUH = base + OFF_BUH, aBUL = base + OFF_BUL;
    const uint32_t aBVH = base + OFF_BVH, aBVL = base + OFF_BVL;

    for (int t = 0; t < 4; t++) {
        // ---- build A tile (q_j * Kp) as bf16 hi/lo + LN stats ----
        {
            const float* kprow = &g_Kp[((size_t)(b * TK + t * 128 + k_a)) * HID + j0];
            float sk = 0.f, sk2 = 0.f, da = 0.f, da2 = 0.f;
#pragma unroll
            for (int g2 = 0; g2 < 4; g2++) {
                float4 v0 = *(const float4*)(kprow + g2 * 8);
                float4 v1 = *(const float4*)(kprow + g2 * 8 + 4);
                float4 q0 = *(const float4*)&sc->qrow[j0 + g2 * 8];
                float4 q1 = *(const float4*)&sc->qrow[j0 + g2 * 8 + 4];
                float a0 = q0.x * v0.x, a1 = q0.y * v0.y, a2 = q0.z * v0.z, a3 = q0.w * v0.w;
                float a4 = q1.x * v1.x, a5 = q1.y * v1.y, a6 = q1.z * v1.z, a7 = q1.w * v1.w;
                sk += v0.x + v0.y + v0.z + v0.w + v1.x + v1.y + v1.z + v1.w;
                sk2 = fmaf(v0.x, v0.x, sk2); sk2 = fmaf(v0.y, v0.y, sk2);
                sk2 = fmaf(v0.z, v0.z, sk2); sk2 = fmaf(v0.w, v0.w, sk2);
                sk2 = fmaf(v1.x, v1.x, sk2); sk2 = fmaf(v1.y, v1.y, sk2);
                sk2 = fmaf(v1.z, v1.z, sk2); sk2 = fmaf(v1.w, v1.w, sk2);
                da += a0 + a1 + a2 + a3 + a4 + a5 + a6 + a7;
                da2 = fmaf(a0, a0, da2); da2 = fmaf(a1, a1, da2);
                da2 = fmaf(a2, a2, da2); da2 = fmaf(a3, a3, da2);
                da2 = fmaf(a4, a4, da2); da2 = fmaf(a5, a5, da2);
                da2 = fmaf(a6, a6, da2); da2 = fmaf(a7, a7, da2);
                __nv_bfloat162 H0 = __floats2bfloat162_rn(a0, a1);
                __nv_bfloat162 H1 = __floats2bfloat162_rn(a2, a3);
                __nv_bfloat162 H2 = __floats2bfloat162_rn(a4, a5);
                __nv_bfloat162 H3 = __floats2bfloat162_rn(a6, a7);
                __nv_bfloat162 L0 = __floats2bfloat162_rn(a0 - __low2float(H0), a1 - __high2float(H0));
                __nv_bfloat162 L1 = __floats2bfloat162_rn(a2 - __low2float(H1), a3 - __high2float(H1));
                __nv_bfloat162 L2 = __floats2bfloat162_rn(a4 - __low2float(H2), a5 - __high2float(H2));
                __nv_bfloat162 L3 = __floats2bfloat162_rn(a6 - __low2float(H3), a7 - __high2float(H3));
                uint32_t ad = (uint32_t)(k_a * ROWB + j0 * 2 + g2 * 16);
                uint4 HI; HI.x = b2u(H0); HI.y = b2u(H1); HI.z = b2u(H2); HI.w = b2u(H3);
                uint4 LO; LO.x = b2u(L0); LO.y = b2u(L1); LO.z = b2u(L2); LO.w = b2u(L3);
                *(uint4*)(cbase + OFF_AH + ad) = HI;
                *(uint4*)(cbase + OFF_AL + ad) = LO;
            }
#pragma unroll
            for (int o = 1; o <= 2; o <<= 1) {
                sk  += __shfl_xor_sync(0xffffffffu, sk,  o);
                sk2 += __shfl_xor_sync(0xffffffffu, sk2, o);
                da  += __shfl_xor_sync(0xffffffffu, da,  o);
                da2 += __shfl_xor_sync(0xffffffffu, da2, o);
            }
            if (quad == 0) {
                float mu = (sqv + sk + da) * inv384;
                float ms = (sq2v + sk2 + da2) * inv384;
                float R0 = rsqrtf(ms - mu * mu + EPSF);
                sc->rr[k_a]  = R0;
                sc->rmu[k_a] = R0 * mu;
            }
        }
        __syncthreads();

        // ---- GEMM: 32k x 32h per warp, u & v, 3-term bf16 split ----
        float accU[2][4][4], accV[2][4][4];
#pragma unroll
        for (int mt = 0; mt < 2; mt++)
#pragma unroll
            for (int nt = 0; nt < 4; nt++)
#pragma unroll
                for (int d = 0; d < 4; d++) { accU[mt][nt][d] = 0.f; accV[mt][nt][d] = 0.f; }

#pragma unroll
        for (int ks = 0; ks < 8; ks++) {
            uint32_t ah0[4], ah1[4], al0[4], al1[4];
            {
                int row = warpK * 32 + (lane & 15);
                int col = ks * 16 + (lane >> 4) * 8;
                uint32_t o0 = (uint32_t)(row * ROWB + col * 2);
                LDSM_X4(ah0, aAH + o0);
                LDSM_X4(ah1, aAH + o0 + 16 * ROWB);
                LDSM_X4(al0, aAL + o0);
                LDSM_X4(al1, aAL + o0 + 16 * ROWB);
            }
            uint32_t brow = (uint32_t)((ks * 16 + (lane & 15)) * ROWB);
#pragma unroll
            for (int nt = 0; nt < 4; nt++) {
                uint32_t boff = brow + (uint32_t)((warpH * 32 + nt * 8) * 2);
                uint32_t bh[2], bl[2];
                LDSM_X2T(bh, aBUH + boff);
                mma16816(accU[0][nt], ah0, bh);
                mma16816(accU[1][nt], ah1, bh);
                mma16816(accU[0][nt], al0, bh);
                mma16816(accU[1][nt], al1, bh);
                LDSM_X2T(bl, aBUL + boff);
                mma16816(accU[0][nt], ah0, bl);
                mma16816(accU[1][nt], ah1, bl);
                LDSM_X2T(bh, aBVH + boff);
                mma16816(accV[0][nt], ah0, bh);
                mma16816(accV[1][nt], ah1, bh);
                mma16816(accV[0][nt], al0, bh);
                mma16816(accV[1][nt], al1, bh);
                LDSM_X2T(bl, aBVL + boff);
                mma16816(accV[0][nt], ah0, bl);
                mma16816(accV[1][nt], ah1, bl);
            }
        }

        // ---- epilogue ----
        float Rr[2][2], RMn[2][2];
        int krows[2][2];
#pragma unroll
        for (int mt = 0; mt < 2; mt++)
#pragma unroll
            for (int rp = 0; rp < 2; rp++) {
                int k = warpK * 32 + mt * 16 + (lane >> 2) + rp * 8;
                krows[mt][rp] = k;
                Rr[mt][rp] = sc->rr[k];
                RMn[mt][rp] = -sc->rmu[k];
            }
        float pr[2][2] = {{0.f, 0.f}, {0.f, 0.f}};
        const size_t gbase = ((size_t)(b * TK + t * 128)) * HID;
#pragma unroll
        for (int nt = 0; nt < 4; nt++) {
            int c0 = warpH * 32 + nt * 8 + 2 * (lane & 3);
            float2 AU = *(const float2*)&sc->AqU[c0];
            float2 AV = *(const float2*)&sc->AqV[c0];
            float2 GU = *(const float2*)&sc->Gu[c0];
            float2 BU = *(const float2*)&sc->Bu[c0];
            float2 GV = *(const float2*)&sc->Gv[c0];
            float2 BV = *(const float2*)&sc->Bv[c0];
            float2 WO = *(const float2*)&sc->Wo[c0];
#pragma unroll
            for (int mt = 0; mt < 2; mt++)
#pragma unroll
                for (int rp = 0; rp < 2; rp++) {
                    float R = Rr[mt][rp], RM = RMn[mt][rp];
                    size_t off = gbase + (size_t)krows[mt][rp] * HID + c0;
                    float2 KU = *(const float2*)&g_KW2u[off];
                    float2 KV = *(const float2*)&g_KW2v[off];
                    float p = 0.f;
                    {
                        float au_ = accU[mt][nt][rp * 2 + 0] + KU.x + AU.x;
                        float av_ = accV[mt][nt][rp * 2 + 0] + KV.x + AV.x;
                        float uu = fmaf(R, au_, fmaf(RM, GU.x, BU.x));
                        float vv = fmaf(R, av_, fmaf(RM, GV.x, BV.x));
                        float gl = 0.5f * vv * (1.0f + erff(vv * 0.70710678118f));
                        p = fmaf(uu * gl, WO.x, p);
                    }
                    {
                        float au_ = accU[mt][nt][rp * 2 + 1] + KU.y + AU.y;
                        float av_ = accV[mt][nt][rp * 2 + 1] + KV.y + AV.y;
                        float uu = fmaf(R, au_, fmaf(RM, GU.y, BU.y));
                        float vv = fmaf(R, av_, fmaf(RM, GV.y, BV.y));
                        float gl = 0.5f * vv * (1.0f + erff(vv * 0.70710678118f));
                        p = fmaf(uu * gl, WO.y, p);
                    }
                    pr[mt][rp] += p;
                }
        }
#pragma unroll
        for (int mt = 0; mt < 2; mt++)
#pragma unroll
            for (int rp = 0; rp < 2; rp++) {
                float v = pr[mt][rp];
                v += __shfl_xor_sync(0xffffffffu, v, 1);
                v += __shfl_xor_sync(0xffffffffu, v, 2);
                if ((lane & 3) == 0) sc->pbuf[warpH][krows[mt][rp]] = v;
            }
        __syncthreads();
        if (tid < 128) {
            float r = sc->pbuf[0][tid] + sc->pbuf[1][tid] + sc->pbuf[2][tid]
                    + sc->pbuf[3][tid] + sc->bo;
            out[(size_t)bq * TK + t * 128 + tid] = r;
        }
        __syncthreads();
    }
}

// ---------------- launch ----------------
extern "C" void kernel_launch(void* const* d_in, const int* in_sizes, int n_in,
                              void* d_out, int out_size) {
    const float* Q    = (const float*)d_in[0];
    const float* K    = (const float*)d_in[1];
    const float* Wq   = (const float*)d_in[2];
    const float* Wk   = (const float*)d_in[3];
    const float* ln_g = (const float*)d_in[4];
    const float* ln_b = (const float*)d_in[5];
    const float* Wu   = (const float*)d_in[6];
    const float* bu   = (const float*)d_in[7];
    const float* Wv   = (const float*)d_in[8];
    const float* bv   = (const float*)d_in[9];
    const float* Wo   = (const float*)d_in[10];
    const float* bo   = (const float*)d_in[11];

    int B = in_sizes[0] / (TQ * QDIM);
    if (B < 1) B = 1;
    if (B > MAXB) B = MAXB;

    cudaFuncSetAttribute(k_main, cudaFuncAttributeMaxDynamicSharedMemorySize, SMEM_BYTES);

    k_wprep<<<HID, HID>>>(ln_g, Wu, Wv);
    k_gb<<<1, HID>>>(ln_g, ln_b, Wu, bu, Wv, bv);
    k_proj<<<2 * B * TQ / PROJ_ROWS, 128>>>(Q, K, Wq, Wk, B);
    k_lin2<<<2 * B * TK / 16, 128>>>(B);
    k_main<<<B * TQ, 512, SMEM_BYTES>>>(Wo, bo, (float*)d_out);
}

// round 7
// speedup vs baseline: 3.0567x; 1.2287x over previous
#include <cuda_runtime.h>
#include <cuda_bf16.h>
#include <math.h>
#include <stdint.h>

#define HID   128
#define TQ    512
#define TK    512
#define QDIM  1024
#define MAXB  2
#define EPSF  1e-5f

#define PADJ   136                 // padded row length (bf16 elems) -> 272 B
#define ROWB   (PADJ * 2)          // 272
#define TILEB  (128 * ROWB)        // 34816

// ---------------- device scratch ----------------
__device__ __align__(16) float g_Qp[MAXB * TQ * HID];
__device__ __align__(16) float g_Kp[MAXB * TK * HID];
__device__ __align__(16) float g_W1u[HID * HID], g_W1v[HID * HID];
__device__ __align__(16) float g_W2u[HID * HID], g_W2v[HID * HID];
__device__ __align__(16) float g_W3u[HID * HID], g_W3v[HID * HID];
__device__ __align__(16) __nv_bfloat16 g_KpH[MAXB * TK * PADJ];
__device__ __align__(16) __nv_bfloat16 g_KpL[MAXB * TK * PADJ];
__device__ __align__(16) float g_AqU[MAXB * TQ * HID], g_AqV[MAXB * TQ * HID];
__device__ float g_Gu[HID], g_Bu[HID], g_Gv[HID], g_Bv[HID];

// ---------------- helpers ----------------
__device__ __forceinline__ uint32_t smem_u32(const void* p) {
    uint32_t a;
    asm("{ .reg .u64 t; cvta.to.shared.u64 t, %1; cvt.u32.u64 %0, t; }" : "=r"(a) : "l"(p));
    return a;
}
__device__ __forceinline__ uint32_t b2u(__nv_bfloat162 h) {
    union { __nv_bfloat162 b; uint32_t u; } x; x.b = h; return x.u;
}
#define LDSM_X4(r, a)                                                        \
    asm volatile("ldmatrix.sync.aligned.m8n8.x4.shared.b16 {%0,%1,%2,%3}, [%4];" \
        : "=r"((r)[0]), "=r"((r)[1]), "=r"((r)[2]), "=r"((r)[3]) : "r"(a))
#define LDSM_X2T(r, a)                                                       \
    asm volatile("ldmatrix.sync.aligned.m8n8.x2.trans.shared.b16 {%0,%1}, [%2];" \
        : "=r"((r)[0]), "=r"((r)[1]) : "r"(a))
#define CP_ASYNC16(dst, src) \
    asm volatile("cp.async.cg.shared.global [%0], [%1], 16;" :: "r"(dst), "l"(src))
#define CP_COMMIT() asm volatile("cp.async.commit_group;" ::: "memory")
#define CP_WAIT0()  asm volatile("cp.async.wait_group 0;" ::: "memory")

__device__ __forceinline__ void mma16816(float* d, const uint32_t* a, const uint32_t* b) {
    asm volatile("mma.sync.aligned.m16n8k16.row.col.f32.bf16.bf16.f32 "
        "{%0,%1,%2,%3}, {%4,%5,%6,%7}, {%8,%9}, {%0,%1,%2,%3};"
        : "+f"(d[0]), "+f"(d[1]), "+f"(d[2]), "+f"(d[3])
        : "r"(a[0]), "r"(a[1]), "r"(a[2]), "r"(a[3]), "r"(b[0]), "r"(b[1]));
}

// ---------------- prologue kernels ----------------
__global__ void k_wprep(const float* __restrict__ g,
                        const float* __restrict__ Wu, const float* __restrict__ Wv) {
    int j = blockIdx.x, h = threadIdx.x;
    float g0 = g[j], g1 = g[HID + j], g2 = g[2 * HID + j];
    g_W1u[j * HID + h] = g0 * Wu[j * HID + h];
    g_W1v[j * HID + h] = g0 * Wv[j * HID + h];
    g_W2u[j * HID + h] = g1 * Wu[(HID + j) * HID + h];
    g_W2v[j * HID + h] = g1 * Wv[(HID + j) * HID + h];
    g_W3u[j * HID + h] = g2 * Wu[(2 * HID + j) * HID + h];
    g_W3v[j * HID + h] = g2 * Wv[(2 * HID + j) * HID + h];
}

__global__ void k_gb(const float* __restrict__ g, const float* __restrict__ bln,
                     const float* __restrict__ Wu, const float* __restrict__ bu,
                     const float* __restrict__ Wv, const float* __restrict__ bv) {
    int h = threadIdx.x;
    float Gu = 0.f, Bu = 0.f, Gv = 0.f, Bv = 0.f;
    for (int c = 0; c < 3 * HID; c++) {
        float wu = Wu[c * HID + h], wv = Wv[c * HID + h];
        float gc = g[c], bc = bln[c];
        Gu = fmaf(gc, wu, Gu); Bu = fmaf(bc, wu, Bu);
        Gv = fmaf(gc, wv, Gv); Bv = fmaf(bc, wv, Bv);
    }
    g_Gu[h] = Gu; g_Bu[h] = Bu + bu[h];
    g_Gv[h] = Gv; g_Bv[h] = Bv + bv[h];
}

#define PROJ_ROWS 16
#define PROJ_DCHUNK 256
__global__ __launch_bounds__(128) void k_proj(const float* __restrict__ Q,
                                              const float* __restrict__ K,
                                              const float* __restrict__ Wq,
                                              const float* __restrict__ Wk, int B) {
    __shared__ __align__(16) float s[PROJ_ROWS][PROJ_DCHUNK];
    int nQ = B * TQ / PROJ_ROWS;
    bool isK = (int)blockIdx.x >= nQ;
    int blk = isK ? (blockIdx.x - nQ) : blockIdx.x;
    const float* X = isK ? K : Q;
    const float* W = isK ? Wk : Wq;
    int row0 = blk * PROJ_ROWS, h = threadIdx.x;
    float acc[PROJ_ROWS];
#pragma unroll
    for (int r = 0; r < PROJ_ROWS; r++) acc[r] = 0.f;
    for (int d0 = 0; d0 < QDIM; d0 += PROJ_DCHUNK) {
        for (int i = threadIdx.x; i < PROJ_ROWS * (PROJ_DCHUNK / 4); i += 128) {
            int r = i / (PROJ_DCHUNK / 4), c4 = i % (PROJ_DCHUNK / 4);
            *(float4*)&s[r][c4 * 4] = *(const float4*)&X[(size_t)(row0 + r) * QDIM + d0 + c4 * 4];
        }
        __syncthreads();
        for (int dd = 0; dd < PROJ_DCHUNK; dd += 4) {
            float w0 = W[(d0 + dd + 0) * HID + h], w1 = W[(d0 + dd + 1) * HID + h];
            float w2 = W[(d0 + dd + 2) * HID + h], w3 = W[(d0 + dd + 3) * HID + h];
#pragma unroll
            for (int r = 0; r < PROJ_ROWS; r++) {
                float4 sv = *(const float4*)&s[r][dd];
                acc[r] = fmaf(sv.x, w0, acc[r]); acc[r] = fmaf(sv.y, w1, acc[r]);
                acc[r] = fmaf(sv.z, w2, acc[r]); acc[r] = fmaf(sv.w, w3, acc[r]);
            }
        }
        __syncthreads();
    }
#pragma unroll
    for (int r = 0; r < PROJ_ROWS; r++) {
        int grow = row0 + r;
        if (isK) g_Kp[(size_t)grow * HID + h] = acc[r];
        else     g_Qp[(size_t)grow * HID + h] = acc[r];
    }
}

// bf16 hi/lo images of Kp, padded rows (LDSM-ready)
__global__ void k_kprep(int B) {
    int k = blockIdx.x;       // over B*TK
    int h = threadIdx.x;      // 0..127
    float v = g_Kp[(size_t)k * HID + h];
    __nv_bfloat16 hi = __float2bfloat16(v);
    g_KpH[(size_t)k * PADJ + h] = hi;
    g_KpL[(size_t)k * PADJ + h] = __float2bfloat16(v - __bfloat162float(hi));
}

// Aq = Qp@W1 (u,v)
__global__ __launch_bounds__(128) void k_lin2(int B) {
    __shared__ __align__(16) float s[16][HID];
    int row0 = blockIdx.x * 16, h = threadIdx.x;
    for (int i = threadIdx.x; i < 16 * 32; i += 128) {
        int r = i >> 5, c = i & 31;
        *(float4*)&s[r][c * 4] = *(const float4*)&g_Qp[(size_t)(row0 + r) * HID + c * 4];
    }
    __syncthreads();
    float au[16], av[16];
#pragma unroll
    for (int r = 0; r < 16; r++) { au[r] = 0.f; av[r] = 0.f; }
    for (int j = 0; j < HID; j++) {
        float wa = g_W1u[j * HID + h], wb = g_W1v[j * HID + h];
#pragma unroll
        for (int r = 0; r < 16; r++) {
            float kv = s[r][j];
            au[r] = fmaf(kv, wa, au[r]); av[r] = fmaf(kv, wb, av[r]);
        }
    }
#pragma unroll
    for (int r = 0; r < 16; r++) {
        g_AqU[(size_t)(row0 + r) * HID + h] = au[r];
        g_AqV[(size_t)(row0 + r) * HID + h] = av[r];
    }
}

// ---------------- main fused kernel ----------------
struct __align__(16) ScalS {
    float qrow[HID];
    float AqU[HID], AqV[HID];
    float Gu[HID], Bu[HID], Gv[HID], Bv[HID], Wo[HID];
    float rr[TK], rmu[TK];
    float pbuf[4][HID];
    float red1[4], red2[4];
    float sq, sq2, bo, pad;
};
#define OFF_BUH 0
#define OFF_BUL (1 * TILEB)
#define OFF_BVH (2 * TILEB)
#define OFF_BVL (3 * TILEB)
#define OFF_AH  (4 * TILEB)
#define OFF_AL  (5 * TILEB)
#define OFF_SCAL (6 * TILEB)
#define SMEM_BYTES (OFF_SCAL + (int)sizeof(ScalS) + 256)

__global__ __launch_bounds__(512, 1) void k_main(const float* __restrict__ Wo_g,
                                                 const float* __restrict__ bo_g,
                                                 float* __restrict__ out) {
    extern __shared__ char smraw[];
    uint32_t sb = smem_u32(smraw);
    uint32_t base = (sb + 127u) & ~127u;
    char* cbase = smraw + (base - sb);
    ScalS* sc = (ScalS*)(cbase + OFF_SCAL);

    const int tid = threadIdx.x;
    const int wrp = tid >> 5, lane = tid & 31;
    const int warpK = wrp & 3, warpH = wrp >> 2;
    const int bq = blockIdx.x, b = bq / TQ;

    const uint32_t aAH  = base + OFF_AH,  aAL  = base + OFF_AL;
    const uint32_t aBUH = base + OFF_BUH, aBUL = base + OFF_BUL;
    const uint32_t aBVH = base + OFF_BVH, aBVL = base + OFF_BVL;

    // prefetch A tile 0 (Kp hi/lo images, contiguous padded rows)
    {
        const char* srcH = (const char*)&g_KpH[(size_t)(b * TK) * PADJ];
        const char* srcL = (const char*)&g_KpL[(size_t)(b * TK) * PADJ];
        for (int i = tid; i < TILEB / 16; i += 512) {
            CP_ASYNC16(aAH + i * 16, srcH + i * 16);
            CP_ASYNC16(aAL + i * 16, srcL + i * 16);
        }
        CP_COMMIT();
    }

    if (tid < HID) {
        sc->qrow[tid] = g_Qp[(size_t)bq * HID + tid];
        sc->AqU[tid] = g_AqU[(size_t)bq * HID + tid];
        sc->AqV[tid] = g_AqV[(size_t)bq * HID + tid];
        sc->Gu[tid] = g_Gu[tid]; sc->Bu[tid] = g_Bu[tid];
        sc->Gv[tid] = g_Gv[tid]; sc->Bv[tid] = g_Bv[tid];
        sc->Wo[tid] = Wo_g[tid];
    }
    if (tid == 0) sc->bo = bo_g[0];
    __syncthreads();

    if (tid < 128) {
        float q = sc->qrow[tid];
        float s = q, s2 = q * q;
#pragma unroll
        for (int o = 16; o; o >>= 1) {
            s  += __shfl_xor_sync(0xffffffffu, s,  o);
            s2 += __shfl_xor_sync(0xffffffffu, s2, o);
        }
        if (lane == 0) { sc->red1[wrp] = s; sc->red2[wrp] = s2; }
    }
    __syncthreads();
    if (tid == 0) {
        sc->sq  = sc->red1[0] + sc->red1[1] + sc->red1[2] + sc->red1[3];
        sc->sq2 = sc->red2[0] + sc->red2[1] + sc->red2[2] + sc->red2[3];
    }
    __syncthreads();
    const float sqv = sc->sq, sq2v = sc->sq2, inv384 = 1.0f / 384.0f;

    // ---- build B_q = diag(q)*W3 + W2 (u,v) as bf16 hi/lo images ----
    for (int i = tid; i < 4096; i += 512) {
        int j = i >> 5, c4 = (i & 31) << 2;
        float qj = sc->qrow[j];
        float4 w3u = *(const float4*)&g_W3u[j * HID + c4];
        float4 w2u = *(const float4*)&g_W2u[j * HID + c4];
        float4 w3v = *(const float4*)&g_W3v[j * HID + c4];
        float4 w2v = *(const float4*)&g_W2v[j * HID + c4];
        float u0 = fmaf(qj, w3u.x, w2u.x), u1 = fmaf(qj, w3u.y, w2u.y);
        float u2 = fmaf(qj, w3u.z, w2u.z), u3 = fmaf(qj, w3u.w, w2u.w);
        float v0 = fmaf(qj, w3v.x, w2v.x), v1 = fmaf(qj, w3v.y, w2v.y);
        float v2 = fmaf(qj, w3v.z, w2v.z), v3 = fmaf(qj, w3v.w, w2v.w);
        __nv_bfloat162 UH0 = __floats2bfloat162_rn(u0, u1), UH1 = __floats2bfloat162_rn(u2, u3);
        __nv_bfloat162 VH0 = __floats2bfloat162_rn(v0, v1), VH1 = __floats2bfloat162_rn(v2, v3);
        __nv_bfloat162 UL0 = __floats2bfloat162_rn(u0 - __low2float(UH0), u1 - __high2float(UH0));
        __nv_bfloat162 UL1 = __floats2bfloat162_rn(u2 - __low2float(UH1), u3 - __high2float(UH1));
        __nv_bfloat162 VL0 = __floats2bfloat162_rn(v0 - __low2float(VH0), v1 - __high2float(VH0));
        __nv_bfloat162 VL1 = __floats2bfloat162_rn(v2 - __low2float(VH1), v3 - __high2float(VH1));
        uint32_t ad = (uint32_t)(j * ROWB + c4 * 2);
        uint2 t0;
        t0.x = b2u(UH0); t0.y = b2u(UH1); *(uint2*)(cbase + OFF_BUH + ad) = t0;
        t0.x = b2u(UL0); t0.y = b2u(UL1); *(uint2*)(cbase + OFF_BUL + ad) = t0;
        t0.x = b2u(VH0); t0.y = b2u(VH1); *(uint2*)(cbase + OFF_BVH + ad) = t0;
        t0.x = b2u(VL0); t0.y = b2u(VL1); *(uint2*)(cbase + OFF_BVL + ad) = t0;
    }

    // ---- per-k LN stats for all 512 k ----
    {
        int k = tid;
        const float* kr = &g_Kp[((size_t)(b * TK + k)) * HID];
        float dqk = 0.f, d22 = 0.f, skv = 0.f, sk2v = 0.f;
#pragma unroll 4
        for (int j = 0; j < HID; j += 4) {
            float4 v = *(const float4*)&kr[j];
            float4 q = *(const float4*)&sc->qrow[j];
            float a0 = q.x * v.x, a1 = q.y * v.y, a2 = q.z * v.z, a3 = q.w * v.w;
            skv += v.x + v.y + v.z + v.w;
            sk2v = fmaf(v.x, v.x, sk2v); sk2v = fmaf(v.y, v.y, sk2v);
            sk2v = fmaf(v.z, v.z, sk2v); sk2v = fmaf(v.w, v.w, sk2v);
            dqk += a0 + a1 + a2 + a3;
            d22 = fmaf(a0, a0, d22); d22 = fmaf(a1, a1, d22);
            d22 = fmaf(a2, a2, d22); d22 = fmaf(a3, a3, d22);
        }
        float mu = (sqv + skv + dqk) * inv384;
        float ms = (sq2v + sk2v + d22) * inv384;
        float R0 = rsqrtf(ms - mu * mu + EPSF);
        sc->rr[k]  = R0;
        sc->rmu[k] = R0 * mu;
    }

    CP_WAIT0();
    __syncthreads();

    for (int t = 0; t < 4; t++) {
        // ---- GEMM: 32k x 32h per warp, u & v, 3-term bf16 split ----
        float accU[2][4][4], accV[2][4][4];
#pragma unroll
        for (int mt = 0; mt < 2; mt++)
#pragma unroll
            for (int nt = 0; nt < 4; nt++)
#pragma unroll
                for (int d = 0; d < 4; d++) { accU[mt][nt][d] = 0.f; accV[mt][nt][d] = 0.f; }

#pragma unroll
        for (int ks = 0; ks < 8; ks++) {
            uint32_t ah0[4], ah1[4], al0[4], al1[4];
            {
                int row = warpK * 32 + (lane & 15);
                int col = ks * 16 + (lane >> 4) * 8;
                uint32_t o0 = (uint32_t)(row * ROWB + col * 2);
                LDSM_X4(ah0, aAH + o0);
                LDSM_X4(ah1, aAH + o0 + 16 * ROWB);
                LDSM_X4(al0, aAL + o0);
                LDSM_X4(al1, aAL + o0 + 16 * ROWB);
            }
            uint32_t brow = (uint32_t)((ks * 16 + (lane & 15)) * ROWB);
#pragma unroll
            for (int nt = 0; nt < 4; nt++) {
                uint32_t boff = brow + (uint32_t)((warpH * 32 + nt * 8) * 2);
                uint32_t bh[2], bl[2];
                LDSM_X2T(bh, aBUH + boff);
                mma16816(accU[0][nt], ah0, bh);
                mma16816(accU[1][nt], ah1, bh);
                mma16816(accU[0][nt], al0, bh);
                mma16816(accU[1][nt], al1, bh);
                LDSM_X2T(bl, aBUL + boff);
                mma16816(accU[0][nt], ah0, bl);
                mma16816(accU[1][nt], ah1, bl);
                LDSM_X2T(bh, aBVH + boff);
                mma16816(accV[0][nt], ah0, bh);
                mma16816(accV[1][nt], ah1, bh);
                mma16816(accV[0][nt], al0, bh);
                mma16816(accV[1][nt], al1, bh);
                LDSM_X2T(bl, aBVL + boff);
                mma16816(accV[0][nt], ah0, bl);
                mma16816(accV[1][nt], ah1, bl);
            }
        }

        // ---- epilogue (no gmem loads; Aq-fold, LN, exact gelu, Wo dot) ----
        float Rr[2][2], RMn[2][2];
        int krows[2][2];
#pragma unroll
        for (int mt = 0; mt < 2; mt++)
#pragma unroll
            for (int rp = 0; rp < 2; rp++) {
                int k = warpK * 32 + mt * 16 + (lane >> 2) + rp * 8;
                krows[mt][rp] = k;
                Rr[mt][rp] = sc->rr[t * 128 + k];
                RMn[mt][rp] = -sc->rmu[t * 128 + k];
            }
        float pr[2][2] = {{0.f, 0.f}, {0.f, 0.f}};
#pragma unroll
        for (int nt = 0; nt < 4; nt++) {
            int c0 = warpH * 32 + nt * 8 + 2 * (lane & 3);
            float2 AU = *(const float2*)&sc->AqU[c0];
            float2 AV = *(const float2*)&sc->AqV[c0];
            float2 GU = *(const float2*)&sc->Gu[c0];
            float2 BU = *(const float2*)&sc->Bu[c0];
            float2 GV = *(const float2*)&sc->Gv[c0];
            float2 BV = *(const float2*)&sc->Bv[c0];
            float2 WO = *(const float2*)&sc->Wo[c0];
#pragma unroll
            for (int mt = 0; mt < 2; mt++)
#pragma unroll
                for (int rp = 0; rp < 2; rp++) {
                    float R = Rr[mt][rp], RM = RMn[mt][rp];
                    float p = 0.f;
                    {
                        float au_ = accU[mt][nt][rp * 2 + 0] + AU.x;
                        float av_ = accV[mt][nt][rp * 2 + 0] + AV.x;
                        float uu = fmaf(R, au_, fmaf(RM, GU.x, BU.x));
                        float vv = fmaf(R, av_, fmaf(RM, GV.x, BV.x));
                        float gl = 0.5f * vv * (1.0f + erff(vv * 0.70710678118f));
                        p = fmaf(uu * gl, WO.x, p);
                    }
                    {
                        float au_ = accU[mt][nt][rp * 2 + 1] + AU.y;
                        float av_ = accV[mt][nt][rp * 2 + 1] + AV.y;
                        float uu = fmaf(R, au_, fmaf(RM, GU.y, BU.y));
                        float vv = fmaf(R, av_, fmaf(RM, GV.y, BV.y));
                        float gl = 0.5f * vv * (1.0f + erff(vv * 0.70710678118f));
                        p = fmaf(uu * gl, WO.y, p);
                    }
                    pr[mt][rp] += p;
                }
        }
#pragma unroll
        for (int mt = 0; mt < 2; mt++)
#pragma unroll
            for (int rp = 0; rp < 2; rp++) {
                float v = pr[mt][rp];
                v += __shfl_xor_sync(0xffffffffu, v, 1);
                v += __shfl_xor_sync(0xffffffffu, v, 2);
                if ((lane & 3) == 0) sc->pbuf[warpH][krows[mt][rp]] = v;
            }
        __syncthreads();   // all warps past GEMM(t) and pbuf writes

        // refill A buffer with tile t+1 while finishing the output
        if (t < 3) {
            const char* srcH = (const char*)&g_KpH[(size_t)(b * TK + (t + 1) * 128) * PADJ];
            const char* srcL = (const char*)&g_KpL[(size_t)(b * TK + (t + 1) * 128) * PADJ];
            for (int i = tid; i < TILEB / 16; i += 512) {
                CP_ASYNC16(aAH + i * 16, srcH + i * 16);
                CP_ASYNC16(aAL + i * 16, srcL + i * 16);
            }
            CP_COMMIT();
        }
        if (tid < 128) {
            float r = sc->pbuf[0][tid] + sc->pbuf[1][tid] + sc->pbuf[2][tid]
                    + sc->pbuf[3][tid] + sc->bo;
            out[(size_t)bq * TK + t * 128 + tid] = r;
        }
        if (t < 3) CP_WAIT0();
        __syncthreads();
    }
}

// ---------------- launch ----------------
extern "C" void kernel_launch(void* const* d_in, const int* in_sizes, int n_in,
                              void* d_out, int out_size) {
    const float* Q    = (const float*)d_in[0];
    const float* K    = (const float*)d_in[1];
    const float* Wq   = (const float*)d_in[2];
    const float* Wk   = (const float*)d_in[3];
    const float* ln_g = (const float*)d_in[4];
    const float* ln_b = (const float*)d_in[5];
    const float* Wu   = (const float*)d_in[6];
    const float* bu   = (const float*)d_in[7];
    const float* Wv   = (const float*)d_in[8];
    const float* bv   = (const float*)d_in[9];
    const float* Wo   = (const float*)d_in[10];
    const float* bo   = (const float*)d_in[11];

    int B = in_sizes[0] / (TQ * QDIM);
    if (B < 1) B = 1;
    if (B > MAXB) B = MAXB;

    cudaFuncSetAttribute(k_main, cudaFuncAttributeMaxDynamicSharedMemorySize, SMEM_BYTES);

    k_wprep<<<HID, HID>>>(ln_g, Wu, Wv);
    k_gb<<<1, HID>>>(ln_g, ln_b, Wu, bu, Wv, bv);
    k_proj<<<2 * B * TQ / PROJ_ROWS, 128>>>(Q, K, Wq, Wk, B);
    k_kprep<<<B * TK, HID>>>(B);
    k_lin2<<<B * TQ / 16, 128>>>(B);
    k_main<<<B * TQ, 512, SMEM_BYTES>>>(Wo, bo, (float*)d_out);
}

// round 8
// speedup vs baseline: 3.4945x; 1.1432x over previous
#include <cuda_runtime.h>
#include <cuda_bf16.h>
#include <cuda_fp16.h>
#include <math.h>
#include <stdint.h>

#define HID   128
#define TQ    512
#define TK    512
#define QDIM  1024
#define MAXB  2
#define EPSF  1e-5f

#define PADJ   136                 // padded row length (fp16 elems) -> 272 B
#define ROWB   (PADJ * 2)          // 272
#define TILEB  (128 * ROWB)        // 34816

// ---------------- device scratch ----------------
__device__ __align__(16) float g_Qp[MAXB * TQ * HID];
__device__ __align__(16) float g_Kp[MAXB * TK * HID];
__device__ __align__(16) float g_W1u[HID * HID], g_W1v[HID * HID];
__device__ __align__(16) float g_W2u[HID * HID], g_W2v[HID * HID];
__device__ __align__(16) float g_W3u[HID * HID], g_W3v[HID * HID];
__device__ __align__(16) __half g_KpH[MAXB * TK * PADJ];
__device__ __align__(16) __half g_KpL[MAXB * TK * PADJ];
__device__ __align__(16) float g_AqU[MAXB * TQ * HID], g_AqV[MAXB * TQ * HID];
__device__ float g_Gu[HID], g_Bu[HID], g_Gv[HID], g_Bv[HID];

// ---------------- helpers ----------------
__device__ __forceinline__ uint32_t smem_u32(const void* p) {
    uint32_t a;
    asm("{ .reg .u64 t; cvta.to.shared.u64 t, %1; cvt.u32.u64 %0, t; }" : "=r"(a) : "l"(p));
    return a;
}
__device__ __forceinline__ uint32_t h2u(__half2 h) {
    union { __half2 b; uint32_t u; } x; x.b = h; return x.u;
}
#define LDSM_X4(r, a)                                                        \
    asm volatile("ldmatrix.sync.aligned.m8n8.x4.shared.b16 {%0,%1,%2,%3}, [%4];" \
        : "=r"((r)[0]), "=r"((r)[1]), "=r"((r)[2]), "=r"((r)[3]) : "r"(a))
#define LDSM_X2T(r, a)                                                       \
    asm volatile("ldmatrix.sync.aligned.m8n8.x2.trans.shared.b16 {%0,%1}, [%2];" \
        : "=r"((r)[0]), "=r"((r)[1]) : "r"(a))
#define CP_ASYNC16(dst, src) \
    asm volatile("cp.async.cg.shared.global [%0], [%1], 16;" :: "r"(dst), "l"(src))
#define CP_COMMIT() asm volatile("cp.async.commit_group;" ::: "memory")
#define CP_WAIT0()  asm volatile("cp.async.wait_group 0;" ::: "memory")

__device__ __forceinline__ void mma16816(float* d, const uint32_t* a, const uint32_t* b) {
    asm volatile("mma.sync.aligned.m16n8k16.row.col.f32.f16.f16.f32 "
        "{%0,%1,%2,%3}, {%4,%5,%6,%7}, {%8,%9}, {%0,%1,%2,%3};"
        : "+f"(d[0]), "+f"(d[1]), "+f"(d[2]), "+f"(d[3])
        : "r"(a[0]), "r"(a[1]), "r"(a[2]), "r"(a[3]), "r"(b[0]), "r"(b[1]));
}

// ---------------- prologue kernels ----------------
__global__ void k_wprep(const float* __restrict__ g,
                        const float* __restrict__ Wu, const float* __restrict__ Wv) {
    int j = blockIdx.x, h = threadIdx.x;
    float g0 = g[j], g1 = g[HID + j], g2 = g[2 * HID + j];
    g_W1u[j * HID + h] = g0 * Wu[j * HID + h];
    g_W1v[j * HID + h] = g0 * Wv[j * HID + h];
    g_W2u[j * HID + h] = g1 * Wu[(HID + j) * HID + h];
    g_W2v[j * HID + h] = g1 * Wv[(HID + j) * HID + h];
    g_W3u[j * HID + h] = g2 * Wu[(2 * HID + j) * HID + h];
    g_W3v[j * HID + h] = g2 * Wv[(2 * HID + j) * HID + h];
}

__global__ void k_gb(const float* __restrict__ g, const float* __restrict__ bln,
                     const float* __restrict__ Wu, const float* __restrict__ bu,
                     const float* __restrict__ Wv, const float* __restrict__ bv) {
    int h = threadIdx.x;
    float Gu = 0.f, Bu = 0.f, Gv = 0.f, Bv = 0.f;
    for (int c = 0; c < 3 * HID; c++) {
        float wu = Wu[c * HID + h], wv = Wv[c * HID + h];
        float gc = g[c], bc = bln[c];
        Gu = fmaf(gc, wu, Gu); Bu = fmaf(bc, wu, Bu);
        Gv = fmaf(gc, wv, Gv); Bv = fmaf(bc, wv, Bv);
    }
    g_Gu[h] = Gu; g_Bu[h] = Bu + bu[h];
    g_Gv[h] = Gv; g_Bv[h] = Bv + bv[h];
}

#define PROJ_ROWS 16
#define PROJ_DCHUNK 256
__global__ __launch_bounds__(128) void k_proj(const float* __restrict__ Q,
                                              const float* __restrict__ K,
                                              const float* __restrict__ Wq,
                                              const float* __restrict__ Wk, int B) {
    __shared__ __align__(16) float s[PROJ_ROWS][PROJ_DCHUNK];
    int nQ = B * TQ / PROJ_ROWS;
    bool isK = (int)blockIdx.x >= nQ;
    int blk = isK ? (blockIdx.x - nQ) : blockIdx.x;
    const float* X = isK ? K : Q;
    const float* W = isK ? Wk : Wq;
    int row0 = blk * PROJ_ROWS, h = threadIdx.x;
    float acc[PROJ_ROWS];
#pragma unroll
    for (int r = 0; r < PROJ_ROWS; r++) acc[r] = 0.f;
    for (int d0 = 0; d0 < QDIM; d0 += PROJ_DCHUNK) {
        for (int i = threadIdx.x; i < PROJ_ROWS * (PROJ_DCHUNK / 4); i += 128) {
            int r = i / (PROJ_DCHUNK / 4), c4 = i % (PROJ_DCHUNK / 4);
            *(float4*)&s[r][c4 * 4] = *(const float4*)&X[(size_t)(row0 + r) * QDIM + d0 + c4 * 4];
        }
        __syncthreads();
        for (int dd = 0; dd < PROJ_DCHUNK; dd += 4) {
            float w0 = W[(d0 + dd + 0) * HID + h], w1 = W[(d0 + dd + 1) * HID + h];
            float w2 = W[(d0 + dd + 2) * HID + h], w3 = W[(d0 + dd + 3) * HID + h];
#pragma unroll
            for (int r = 0; r < PROJ_ROWS; r++) {
                float4 sv = *(const float4*)&s[r][dd];
                acc[r] = fmaf(sv.x, w0, acc[r]); acc[r] = fmaf(sv.y, w1, acc[r]);
                acc[r] = fmaf(sv.z, w2, acc[r]); acc[r] = fmaf(sv.w, w3, acc[r]);
            }
        }
        __syncthreads();
    }
#pragma unroll
    for (int r = 0; r < PROJ_ROWS; r++) {
        int grow = row0 + r;
        if (isK) g_Kp[(size_t)grow * HID + h] = acc[r];
        else     g_Qp[(size_t)grow * HID + h] = acc[r];
    }
}

// fp16 hi/lo images of Kp, padded rows (LDSM-ready)
__global__ void k_kprep(int B) {
    int k = blockIdx.x;       // over B*TK
    int h = threadIdx.x;      // 0..127
    float v = g_Kp[(size_t)k * HID + h];
    __half hi = __float2half_rn(v);
    g_KpH[(size_t)k * PADJ + h] = hi;
    g_KpL[(size_t)k * PADJ + h] = __float2half_rn(v - __half2float(hi));
}

// Aq = Qp@W1 (u,v)
__global__ __launch_bounds__(128) void k_lin2(int B) {
    __shared__ __align__(16) float s[16][HID];
    int row0 = blockIdx.x * 16, h = threadIdx.x;
    for (int i = threadIdx.x; i < 16 * 32; i += 128) {
        int r = i >> 5, c = i & 31;
        *(float4*)&s[r][c * 4] = *(const float4*)&g_Qp[(size_t)(row0 + r) * HID + c * 4];
    }
    __syncthreads();
    float au[16], av[16];
#pragma unroll
    for (int r = 0; r < 16; r++) { au[r] = 0.f; av[r] = 0.f; }
    for (int j = 0; j < HID; j++) {
        float wa = g_W1u[j * HID + h], wb = g_W1v[j * HID + h];
#pragma unroll
        for (int r = 0; r < 16; r++) {
            float kv = s[r][j];
            au[r] = fmaf(kv, wa, au[r]); av[r] = fmaf(kv, wb, av[r]);
        }
    }
#pragma unroll
    for (int r = 0; r < 16; r++) {
        g_AqU[(size_t)(row0 + r) * HID + h] = au[r];
        g_AqV[(size_t)(row0 + r) * HID + h] = av[r];
    }
}

// ---------------- main fused kernel ----------------
struct __align__(16) ScalS {
    float qrow[HID];
    float AqU[HID], AqV[HID];
    float Gu[HID], Bu[HID], Gv[HID], Bv[HID], Wo[HID];
    float rr[TK], rmu[TK];
    float pbuf[4][HID];
    float red1[4], red2[4];
    float sq, sq2, bo, pad;
};
#define OFF_BU  0
#define OFF_BV  (1 * TILEB)
#define OFF_A0H (2 * TILEB)   // A buffers: [A0H][A0L][A1H][A1L]
#define OFF_SCAL (6 * TILEB)
#define SMEM_BYTES (OFF_SCAL + (int)sizeof(ScalS) + 256)

__global__ __launch_bounds__(512, 1) void k_main(const float* __restrict__ Wo_g,
                                                 const float* __restrict__ bo_g,
                                                 float* __restrict__ out) {
    extern __shared__ char smraw[];
    uint32_t sb = smem_u32(smraw);
    uint32_t base = (sb + 127u) & ~127u;
    char* cbase = smraw + (base - sb);
    ScalS* sc = (ScalS*)(cbase + OFF_SCAL);

    const int tid = threadIdx.x;
    const int wrp = tid >> 5, lane = tid & 31;
    const int warpK = wrp & 3, warpH = wrp >> 2;
    const int bq = blockIdx.x, b = bq / TQ;

    const uint32_t aBU = base + OFF_BU, aBV = base + OFF_BV;

    // prefetch A tile 0 into buffer 0
    {
        const char* srcH = (const char*)&g_KpH[(size_t)(b * TK) * PADJ];
        const char* srcL = (const char*)&g_KpL[(size_t)(b * TK) * PADJ];
        uint32_t dH = base + OFF_A0H, dL = dH + TILEB;
        for (int i = tid; i < TILEB / 16; i += 512) {
            CP_ASYNC16(dH + i * 16, srcH + i * 16);
            CP_ASYNC16(dL + i * 16, srcL + i * 16);
        }
        CP_COMMIT();
    }

    if (tid < HID) {
        sc->qrow[tid] = g_Qp[(size_t)bq * HID + tid];
        sc->AqU[tid] = g_AqU[(size_t)bq * HID + tid];
        sc->AqV[tid] = g_AqV[(size_t)bq * HID + tid];
        sc->Gu[tid] = g_Gu[tid]; sc->Bu[tid] = g_Bu[tid];
        sc->Gv[tid] = g_Gv[tid]; sc->Bv[tid] = g_Bv[tid];
        sc->Wo[tid] = Wo_g[tid];
    }
    if (tid == 0) sc->bo = bo_g[0];
    __syncthreads();

    if (tid < 128) {
        float q = sc->qrow[tid];
        float s = q, s2 = q * q;
#pragma unroll
        for (int o = 16; o; o >>= 1) {
            s  += __shfl_xor_sync(0xffffffffu, s,  o);
            s2 += __shfl_xor_sync(0xffffffffu, s2, o);
        }
        if (lane == 0) { sc->red1[wrp] = s; sc->red2[wrp] = s2; }
    }
    __syncthreads();
    if (tid == 0) {
        sc->sq  = sc->red1[0] + sc->red1[1] + sc->red1[2] + sc->red1[3];
        sc->sq2 = sc->red2[0] + sc->red2[1] + sc->red2[2] + sc->red2[3];
    }
    __syncthreads();
    const float sqv = sc->sq, sq2v = sc->sq2, inv384 = 1.0f / 384.0f;

    // ---- build B_q = diag(q)*W3 + W2 (u,v) as single fp16 images ----
    for (int i = tid; i < 4096; i += 512) {
        int j = i >> 5, c4 = (i & 31) << 2;
        float qj = sc->qrow[j];
        float4 w3u = *(const float4*)&g_W3u[j * HID + c4];
        float4 w2u = *(const float4*)&g_W2u[j * HID + c4];
        float4 w3v = *(const float4*)&g_W3v[j * HID + c4];
        float4 w2v = *(const float4*)&g_W2v[j * HID + c4];
        __half2 U0 = __floats2half2_rn(fmaf(qj, w3u.x, w2u.x), fmaf(qj, w3u.y, w2u.y));
        __half2 U1 = __floats2half2_rn(fmaf(qj, w3u.z, w2u.z), fmaf(qj, w3u.w, w2u.w));
        __half2 V0 = __floats2half2_rn(fmaf(qj, w3v.x, w2v.x), fmaf(qj, w3v.y, w2v.y));
        __half2 V1 = __floats2half2_rn(fmaf(qj, w3v.z, w2v.z), fmaf(qj, w3v.w, w2v.w));
        uint32_t ad = (uint32_t)(j * ROWB + c4 * 2);
        uint2 t0;
        t0.x = h2u(U0); t0.y = h2u(U1); *(uint2*)(cbase + OFF_BU + ad) = t0;
        t0.x = h2u(V0); t0.y = h2u(V1); *(uint2*)(cbase + OFF_BV + ad) = t0;
    }

    // ---- per-k LN stats for all 512 k ----
    {
        int k = tid;
        const float* kr = &g_Kp[((size_t)(b * TK + k)) * HID];
        float dqk = 0.f, d22 = 0.f, skv = 0.f, sk2v = 0.f;
#pragma unroll 4
        for (int j = 0; j < HID; j += 4) {
            float4 v = *(const float4*)&kr[j];
            float4 q = *(const float4*)&sc->qrow[j];
            float a0 = q.x * v.x, a1 = q.y * v.y, a2 = q.z * v.z, a3 = q.w * v.w;
            skv += v.x + v.y + v.z + v.w;
            sk2v = fmaf(v.x, v.x, sk2v); sk2v = fmaf(v.y, v.y, sk2v);
            sk2v = fmaf(v.z, v.z, sk2v); sk2v = fmaf(v.w, v.w, sk2v);
            dqk += a0 + a1 + a2 + a3;
            d22 = fmaf(a0, a0, d22); d22 = fmaf(a1, a1, d22);
            d22 = fmaf(a2, a2, d22); d22 = fmaf(a3, a3, d22);
        }
        float mu = (sqv + skv + dqk) * inv384;
        float ms = (sq2v + sk2v + d22) * inv384;
        float R0 = rsqrtf(ms - mu * mu + EPSF);
        sc->rr[k]  = R0;
        sc->rmu[k] = R0 * mu;
    }

    for (int t = 0; t < 4; t++) {
        CP_WAIT0();          // my cp.async for tile t complete
        __syncthreads();     // everyone's complete

        // kick off prefetch of tile t+1 into the other A buffer (fully hidden)
        if (t < 3) {
            const char* srcH = (const char*)&g_KpH[(size_t)(b * TK + (t + 1) * 128) * PADJ];
            const char* srcL = (const char*)&g_KpL[(size_t)(b * TK + (t + 1) * 128) * PADJ];
            uint32_t dH = base + OFF_A0H + (uint32_t)(((t + 1) & 1) * 2 * TILEB);
            uint32_t dL = dH + TILEB;
            for (int i = tid; i < TILEB / 16; i += 512) {
                CP_ASYNC16(dH + i * 16, srcH + i * 16);
                CP_ASYNC16(dL + i * 16, srcL + i * 16);
            }
            CP_COMMIT();
        }

        const uint32_t aAH = base + OFF_A0H + (uint32_t)((t & 1) * 2 * TILEB);
        const uint32_t aAL = aAH + TILEB;

        // ---- GEMM: 32k x 32h per warp, u & v, 2-term fp16 split (A exact, B fp16) ----
        float accU[2][4][4], accV[2][4][4];
#pragma unroll
        for (int mt = 0; mt < 2; mt++)
#pragma unroll
            for (int nt = 0; nt < 4; nt++)
#pragma unroll
                for (int d = 0; d < 4; d++) { accU[mt][nt][d] = 0.f; accV[mt][nt][d] = 0.f; }

#pragma unroll
        for (int ks = 0; ks < 8; ks++) {
            uint32_t ah0[4], ah1[4], al0[4], al1[4];
            {
                int row = warpK * 32 + (lane & 15);
                int col = ks * 16 + (lane >> 4) * 8;
                uint32_t o0 = (uint32_t)(row * ROWB + col * 2);
                LDSM_X4(ah0, aAH + o0);
                LDSM_X4(ah1, aAH + o0 + 16 * ROWB);
                LDSM_X4(al0, aAL + o0);
                LDSM_X4(al1, aAL + o0 + 16 * ROWB);
            }
            uint32_t brow = (uint32_t)((ks * 16 + (lane & 15)) * ROWB);
#pragma unroll
            for (int nt = 0; nt < 4; nt++) {
                uint32_t boff = brow + (uint32_t)((warpH * 32 + nt * 8) * 2);
                uint32_t bu2[2], bv2[2];
                LDSM_X2T(bu2, aBU + boff);
                mma16816(accU[0][nt], ah0, bu2);
                mma16816(accU[1][nt], ah1, bu2);
                mma16816(accU[0][nt], al0, bu2);
                mma16816(accU[1][nt], al1, bu2);
                LDSM_X2T(bv2, aBV + boff);
                mma16816(accV[0][nt], ah0, bv2);
                mma16816(accV[1][nt], ah1, bv2);
                mma16816(accV[0][nt], al0, bv2);
                mma16816(accV[1][nt], al1, bv2);
            }
        }

        // ---- epilogue (no gmem loads; Aq-fold, LN, exact gelu, Wo dot) ----
        float Rr[2][2], RMn[2][2];
        int krows[2][2];
#pragma unroll
        for (int mt = 0; mt < 2; mt++)
#pragma unroll
            for (int rp = 0; rp < 2; rp++) {
                int k = warpK * 32 + mt * 16 + (lane >> 2) + rp * 8;
                krows[mt][rp] = k;
                Rr[mt][rp] = sc->rr[t * 128 + k];
                RMn[mt][rp] = -sc->rmu[t * 128 + k];
            }
        float pr[2][2] = {{0.f, 0.f}, {0.f, 0.f}};
#pragma unroll
        for (int nt = 0; nt < 4; nt++) {
            int c0 = warpH * 32 + nt * 8 + 2 * (lane & 3);
            float2 AU = *(const float2*)&sc->AqU[c0];
            float2 AV = *(const float2*)&sc->AqV[c0];
            float2 GU = *(const float2*)&sc->Gu[c0];
            float2 BU = *(const float2*)&sc->Bu[c0];
            float2 GV = *(const float2*)&sc->Gv[c0];
            float2 BV = *(const float2*)&sc->Bv[c0];
            float2 WO = *(const float2*)&sc->Wo[c0];
#pragma unroll
            for (int mt = 0; mt < 2; mt++)
#pragma unroll
                for (int rp = 0; rp < 2; rp++) {
                    float R = Rr[mt][rp], RM = RMn[mt][rp];
                    float p = 0.f;
                    {
                        float au_ = accU[mt][nt][rp * 2 + 0] + AU.x;
                        float av_ = accV[mt][nt][rp * 2 + 0] + AV.x;
                        float uu = fmaf(R, au_, fmaf(RM, GU.x, BU.x));
                        float vv = fmaf(R, av_, fmaf(RM, GV.x, BV.x));
                        float gl = 0.5f * vv * (1.0f + erff(vv * 0.70710678118f));
                        p = fmaf(uu * gl, WO.x, p);
                    }
                    {
                        float au_ = accU[mt][nt][rp * 2 + 1] + AU.y;
                        float av_ = accV[mt][nt][rp * 2 + 1] + AV.y;
                        float uu = fmaf(R, au_, fmaf(RM, GU.y, BU.y));
                        float vv = fmaf(R, av_, fmaf(RM, GV.y, BV.y));
                        float gl = 0.5f * vv * (1.0f + erff(vv * 0.70710678118f));
                        p = fmaf(uu * gl, WO.y, p);
                    }
                    pr[mt][rp] += p;
                }
        }
#pragma unroll
        for (int mt = 0; mt < 2; mt++)
#pragma unroll
            for (int rp = 0; rp < 2; rp++) {
                float v = pr[mt][rp];
                v += __shfl_xor_sync(0xffffffffu, v, 1);
                v += __shfl_xor_sync(0xffffffffu, v, 2);
                if ((lane & 3) == 0) sc->pbuf[warpH][krows[mt][rp]] = v;
            }
        __syncthreads();
        if (tid < 128) {
            float r = sc->pbuf[0][tid] + sc->pbuf[1][tid] + sc->pbuf[2][tid]
                    + sc->pbuf[3][tid] + sc->bo;
            out[(size_t)bq * TK + t * 128 + tid] = r;
        }
        __syncthreads();
    }
}

// ---------------- launch ----------------
extern "C" void kernel_launch(void* const* d_in, const int* in_sizes, int n_in,
                              void* d_out, int out_size) {
    const float* Q    = (const float*)d_in[0];
    const float* K    = (const float*)d_in[1];
    const float* Wq   = (const float*)d_in[2];
    const float* Wk   = (const float*)d_in[3];
    const float* ln_g = (const float*)d_in[4];
    const float* ln_b = (const float*)d_in[5];
    const float* Wu   = (const float*)d_in[6];
    const float* bu   = (const float*)d_in[7];
    const float* Wv   = (const float*)d_in[8];
    const float* bv   = (const float*)d_in[9];
    const float* Wo   = (const float*)d_in[10];
    const float* bo   = (const float*)d_in[11];

    int B = in_sizes[0] / (TQ * QDIM);
    if (B < 1) B = 1;
    if (B > MAXB) B = MAXB;

    cudaFuncSetAttribute(k_main, cudaFuncAttributeMaxDynamicSharedMemorySize, SMEM_BYTES);

    k_wprep<<<HID, HID>>>(ln_g, Wu, Wv);
    k_gb<<<1, HID>>>(ln_g, ln_b, Wu, bu, Wv, bv);
    k_proj<<<2 * B * TQ / PROJ_ROWS, 128>>>(Q, K, Wq, Wk, B);
    k_kprep<<<B * TK, HID>>>(B);
    k_lin2<<<B * TQ / 16, 128>>>(B);
    k_main<<<B * TQ, 512, SMEM_BYTES>>>(Wo, bo, (float*)d_out);
}

// round 13
// speedup vs baseline: 4.1524x; 1.1883x over previous
#include <cuda_runtime.h>
#include <cuda_bf16.h>
#include <cuda_fp16.h>
#include <math.h>
#include <stdint.h>

#define HID   128
#define TQ    512
#define TK    512
#define QDIM  1024
#define MAXB  2
#define EPSF  1e-5f

#define PADJ   136                 // padded row length (fp16 elems) -> 272 B
#define ROWB   (PADJ * 2)          // 272
#define TILEB  (128 * ROWB)        // 34816

// ---------------- device scratch ----------------
__device__ __align__(16) float g_Qp[MAXB * TQ * HID];
__device__ __align__(16) float g_Kp[MAXB * TK * HID];
__device__ __align__(16) float g_W1u[HID * HID], g_W1v[HID * HID];
__device__ __align__(16) float g_W2u[HID * HID], g_W2v[HID * HID];
__device__ __align__(16) float g_W3u[HID * HID], g_W3v[HID * HID];
__device__ __align__(16) __half g_KpH[MAXB * TK * PADJ];
__device__ __align__(16) float g_AqU[MAXB * TQ * HID], g_AqV[MAXB * TQ * HID];
__device__ float g_Gu[HID], g_Bu[HID], g_Gv[HID], g_Bv[HID];

// ---------------- helpers ----------------
__device__ __forceinline__ uint32_t smem_u32(const void* p) {
    uint32_t a;
    asm("{ .reg .u64 t; cvta.to.shared.u64 t, %1; cvt.u32.u64 %0, t; }" : "=r"(a) : "l"(p));
    return a;
}
__device__ __forceinline__ uint32_t h2u(__half2 h) {
    union { __half2 b; uint32_t u; } x; x.b = h; return x.u;
}
#define LDSM_X4(r, a)                                                        \
    asm volatile("ldmatrix.sync.aligned.m8n8.x4.shared.b16 {%0,%1,%2,%3}, [%4];" \
        : "=r"((r)[0]), "=r"((r)[1]), "=r"((r)[2]), "=r"((r)[3]) : "r"(a))
#define LDSM_X2T(r, a)                                                       \
    asm volatile("ldmatrix.sync.aligned.m8n8.x2.trans.shared.b16 {%0,%1}, [%2];" \
        : "=r"((r)[0]), "=r"((r)[1]) : "r"(a))
#define CP_ASYNC16(dst, src) \
    asm volatile("cp.async.cg.shared.global [%0], [%1], 16;" :: "r"(dst), "l"(src))
#define CP_COMMIT() asm volatile("cp.async.commit_group;" ::: "memory")
#define CP_WAIT0()  asm volatile("cp.async.wait_group 0;" ::: "memory")

__device__ __forceinline__ void mma16816(float* d, const uint32_t* a, const uint32_t* b) {
    asm volatile("mma.sync.aligned.m16n8k16.row.col.f32.f16.f16.f32 "
        "{%0,%1,%2,%3}, {%4,%5,%6,%7}, {%8,%9}, {%0,%1,%2,%3};"
        : "+f"(d[0]), "+f"(d[1]), "+f"(d[2]), "+f"(d[3])
        : "r"(a[0]), "r"(a[1]), "r"(a[2]), "r"(a[3]), "r"(b[0]), "r"(b[1]));
}

// ---------------- prologue kernels ----------------
__global__ void k_wprep(const float* __restrict__ g,
                        const float* __restrict__ Wu, const float* __restrict__ Wv) {
    int j = blockIdx.x, h = threadIdx.x;
    float g0 = g[j], g1 = g[HID + j], g2 = g[2 * HID + j];
    g_W1u[j * HID + h] = g0 * Wu[j * HID + h];
    g_W1v[j * HID + h] = g0 * Wv[j * HID + h];
    g_W2u[j * HID + h] = g1 * Wu[(HID + j) * HID + h];
    g_W2v[j * HID + h] = g1 * Wv[(HID + j) * HID + h];
    g_W3u[j * HID + h] = g2 * Wu[(2 * HID + j) * HID + h];
    g_W3v[j * HID + h] = g2 * Wv[(2 * HID + j) * HID + h];
}

__global__ void k_gb(const float* __restrict__ g, const float* __restrict__ bln,
                     const float* __restrict__ Wu, const float* __restrict__ bu,
                     const float* __restrict__ Wv, const float* __restrict__ bv) {
    int h = threadIdx.x;
    float Gu = 0.f, Bu = 0.f, Gv = 0.f, Bv = 0.f;
    for (int c = 0; c < 3 * HID; c++) {
        float wu = Wu[c * HID + h], wv = Wv[c * HID + h];
        float gc = g[c], bc = bln[c];
        Gu = fmaf(gc, wu, Gu); Bu = fmaf(bc, wu, Bu);
        Gv = fmaf(gc, wv, Gv); Bv = fmaf(bc, wv, Bv);
    }
    g_Gu[h] = Gu; g_Bu[h] = Bu + bu[h];
    g_Gv[h] = Gv; g_Bv[h] = Bv + bv[h];
}

#define PROJ_ROWS 16
#define PROJ_DCHUNK 256
__global__ __launch_bounds__(128) void k_proj(const float* __restrict__ Q,
                                              const float* __restrict__ K,
                                              const float* __restrict__ Wq,
                                              const float* __restrict__ Wk, int B) {
    __shared__ __align__(16) float s[PROJ_ROWS][PROJ_DCHUNK];
    int nQ = B * TQ / PROJ_ROWS;
    bool isK = (int)blockIdx.x >= nQ;
    int blk = isK ? (blockIdx.x - nQ) : blockIdx.x;
    const float* X = isK ? K : Q;
    const float* W = isK ? Wk : Wq;
    int row0 = blk * PROJ_ROWS, h = threadIdx.x;
    float acc[PROJ_ROWS];
#pragma unroll
    for (int r = 0; r < PROJ_ROWS; r++) acc[r] = 0.f;
    for (int d0 = 0; d0 < QDIM; d0 += PROJ_DCHUNK) {
        for (int i = threadIdx.x; i < PROJ_ROWS * (PROJ_DCHUNK / 4); i += 128) {
            int r = i / (PROJ_DCHUNK / 4), c4 = i % (PROJ_DCHUNK / 4);
            *(float4*)&s[r][c4 * 4] = *(const float4*)&X[(size_t)(row0 + r) * QDIM + d0 + c4 * 4];
        }
        __syncthreads();
        for (int dd = 0; dd < PROJ_DCHUNK; dd += 4) {
            float w0 = W[(d0 + dd + 0) * HID + h], w1 = W[(d0 + dd + 1) * HID + h];
            float w2 = W[(d0 + dd + 2) * HID + h], w3 = W[(d0 + dd + 3) * HID + h];
#pragma unroll
            for (int r = 0; r < PROJ_ROWS; r++) {
                float4 sv = *(const float4*)&s[r][dd];
                acc[r] = fmaf(sv.x, w0, acc[r]); acc[r] = fmaf(sv.y, w1, acc[r]);
                acc[r] = fmaf(sv.z, w2, acc[r]); acc[r] = fmaf(sv.w, w3, acc[r]);
            }
        }
        __syncthreads();
    }
#pragma unroll
    for (int r = 0; r < PROJ_ROWS; r++) {
        int grow = row0 + r;
        if (isK) g_Kp[(size_t)grow * HID + h] = acc[r];
        else     g_Qp[(size_t)grow * HID + h] = acc[r];
    }
}

// fp16 image of Kp, padded rows (LDSM-ready)
__global__ void k_kprep(int B) {
    int k = blockIdx.x;       // over B*TK
    int h = threadIdx.x;      // 0..127
    g_KpH[(size_t)k * PADJ + h] = __float2half_rn(g_Kp[(size_t)k * HID + h]);
}

// Aq = Qp@W1 (u,v)
__global__ __launch_bounds__(128) void k_lin2(int B) {
    __shared__ __align__(16) float s[16][HID];
    int row0 = blockIdx.x * 16, h = threadIdx.x;
    for (int i = threadIdx.x; i < 16 * 32; i += 128) {
        int r = i >> 5, c = i & 31;
        *(float4*)&s[r][c * 4] = *(const float4*)&g_Qp[(size_t)(row0 + r) * HID + c * 4];
    }
    __syncthreads();
    float au[16], av[16];
#pragma unroll
    for (int r = 0; r < 16; r++) { au[r] = 0.f; av[r] = 0.f; }
    for (int j = 0; j < HID; j++) {
        float wa = g_W1u[j * HID + h], wb = g_W1v[j * HID + h];
#pragma unroll
        for (int r = 0; r < 16; r++) {
            float kv = s[r][j];
            au[r] = fmaf(kv, wa, au[r]); av[r] = fmaf(kv, wb, av[r]);
        }
    }
#pragma unroll
    for (int r = 0; r < 16; r++) {
        g_AqU[(size_t)(row0 + r) * HID + h] = au[r];
        g_AqV[(size_t)(row0 + r) * HID + h] = av[r];
    }
}

// ---------------- main fused kernel ----------------
struct __align__(16) ScalS {
    float qrow[HID];
    float AqU[HID], AqV[HID];
    float Gu[HID], Bu[HID], Gv[HID], Bv[HID], Wo[HID];
    float rr[TK], rmu[TK];
    float pbuf[4][HID];
    float red1[4], red2[4];
    float sq, sq2, bo, pad;
};
#define OFF_BU  0
#define OFF_BV  (1 * TILEB)
#define OFF_A0  (2 * TILEB)   // A buffers: [A0][A1] (hi-only fp16)
#define OFF_SCAL (4 * TILEB)
#define SMEM_BYTES (OFF_SCAL + (int)sizeof(ScalS) + 256)

__global__ __launch_bounds__(512, 1) void k_main(const float* __restrict__ Wo_g,
                                                 const float* __restrict__ bo_g,
                                                 float* __restrict__ out) {
    extern __shared__ char smraw[];
    uint32_t sb = smem_u32(smraw);
    uint32_t base = (sb + 127u) & ~127u;
    char* cbase = smraw + (base - sb);
    ScalS* sc = (ScalS*)(cbase + OFF_SCAL);

    const int tid = threadIdx.x;
    const int wrp = tid >> 5, lane = tid & 31;
    const int warpK = wrp & 3, warpH = wrp >> 2;
    const int bq = blockIdx.x, b = bq / TQ;

    const uint32_t aBU = base + OFF_BU, aBV = base + OFF_BV;

    // prefetch A tile 0 into buffer 0
    {
        const char* srcH = (const char*)&g_KpH[(size_t)(b * TK) * PADJ];
        uint32_t dH = base + OFF_A0;
        for (int i = tid; i < TILEB / 16; i += 512)
            CP_ASYNC16(dH + i * 16, srcH + i * 16);
        CP_COMMIT();
    }

    if (tid < HID) {
        sc->qrow[tid] = g_Qp[(size_t)bq * HID + tid];
        sc->AqU[tid] = g_AqU[(size_t)bq * HID + tid];
        sc->AqV[tid] = g_AqV[(size_t)bq * HID + tid];
        sc->Gu[tid] = g_Gu[tid]; sc->Bu[tid] = g_Bu[tid];
        sc->Gv[tid] = g_Gv[tid]; sc->Bv[tid] = g_Bv[tid];
        sc->Wo[tid] = Wo_g[tid];
    }
    if (tid == 0) sc->bo = bo_g[0];
    __syncthreads();

    if (tid < 128) {
        float q = sc->qrow[tid];
        float s = q, s2 = q * q;
#pragma unroll
        for (int o = 16; o; o >>= 1) {
            s  += __shfl_xor_sync(0xffffffffu, s,  o);
            s2 += __shfl_xor_sync(0xffffffffu, s2, o);
        }
        if (lane == 0) { sc->red1[wrp] = s; sc->red2[wrp] = s2; }
    }
    __syncthreads();
    if (tid == 0) {
        sc->sq  = sc->red1[0] + sc->red1[1] + sc->red1[2] + sc->red1[3];
        sc->sq2 = sc->red2[0] + sc->red2[1] + sc->red2[2] + sc->red2[3];
    }
    __syncthreads();
    const float sqv = sc->sq, sq2v = sc->sq2, inv384 = 1.0f / 384.0f;

    // ---- build B_q = diag(q)*W3 + W2 (u,v) as single fp16 images ----
    for (int i = tid; i < 4096; i += 512) {
        int j = i >> 5, c4 = (i & 31) << 2;
        float qj = sc->qrow[j];
        float4 w3u = *(const float4*)&g_W3u[j * HID + c4];
        float4 w2u = *(const float4*)&g_W2u[j * HID + c4];
        float4 w3v = *(const float4*)&g_W3v[j * HID + c4];
        float4 w2v = *(const float4*)&g_W2v[j * HID + c4];
        __half2 U0 = __floats2half2_rn(fmaf(qj, w3u.x, w2u.x), fmaf(qj, w3u.y, w2u.y));
        __half2 U1 = __floats2half2_rn(fmaf(qj, w3u.z, w2u.z), fmaf(qj, w3u.w, w2u.w));
        __half2 V0 = __floats2half2_rn(fmaf(qj, w3v.x, w2v.x), fmaf(qj, w3v.y, w2v.y));
        __half2 V1 = __floats2half2_rn(fmaf(qj, w3v.z, w2v.z), fmaf(qj, w3v.w, w2v.w));
        uint32_t ad = (uint32_t)(j * ROWB + c4 * 2);
        uint2 t0;
        t0.x = h2u(U0); t0.y = h2u(U1); *(uint2*)(cbase + OFF_BU + ad) = t0;
        t0.x = h2u(V0); t0.y = h2u(V1); *(uint2*)(cbase + OFF_BV + ad) = t0;
    }

    // ---- per-k LN stats for all 512 k (exact fp32) ----
    {
        int k = tid;
        const float* kr = &g_Kp[((size_t)(b * TK + k)) * HID];
        float dqk = 0.f, d22 = 0.f, skv = 0.f, sk2v = 0.f;
#pragma unroll 4
        for (int j = 0; j < HID; j += 4) {
            float4 v = *(const float4*)&kr[j];
            float4 q = *(const float4*)&sc->qrow[j];
            float a0 = q.x * v.x, a1 = q.y * v.y, a2 = q.z * v.z, a3 = q.w * v.w;
            skv += v.x + v.y + v.z + v.w;
            sk2v = fmaf(v.x, v.x, sk2v); sk2v = fmaf(v.y, v.y, sk2v);
            sk2v = fmaf(v.z, v.z, sk2v); sk2v = fmaf(v.w, v.w, sk2v);
            dqk += a0 + a1 + a2 + a3;
            d22 = fmaf(a0, a0, d22); d22 = fmaf(a1, a1, d22);
            d22 = fmaf(a2, a2, d22); d22 = fmaf(a3, a3, d22);
        }
        float mu = (sqv + skv + dqk) * inv384;
        float ms = (sq2v + sk2v + d22) * inv384;
        float R0 = rsqrtf(ms - mu * mu + EPSF);
        sc->rr[k]  = R0;
        sc->rmu[k] = R0 * mu;
    }

    for (int t = 0; t < 4; t++) {
        CP_WAIT0();          // my cp.async for tile t complete
        __syncthreads();     // everyone's complete

        // kick off prefetch of tile t+1 into the other A buffer (fully hidden)
        if (t < 3) {
            const char* srcH = (const char*)&g_KpH[(size_t)(b * TK + (t + 1) * 128) * PADJ];
            uint32_t dH = base + OFF_A0 + (uint32_t)(((t + 1) & 1) * TILEB);
            for (int i = tid; i < TILEB / 16; i += 512)
                CP_ASYNC16(dH + i * 16, srcH + i * 16);
            CP_COMMIT();
        }

        const uint32_t aA = base + OFF_A0 + (uint32_t)((t & 1) * TILEB);

        // ---- GEMM: 32k x 32h per warp, u & v, single fp16 term ----
        float accU[2][4][4], accV[2][4][4];
#pragma unroll
        for (int mt = 0; mt < 2; mt++)
#pragma unroll
            for (int nt = 0; nt < 4; nt++)
#pragma unroll
                for (int d = 0; d < 4; d++) { accU[mt][nt][d] = 0.f; accV[mt][nt][d] = 0.f; }

#pragma unroll
        for (int ks = 0; ks < 8; ks++) {
            uint32_t ah0[4], ah1[4];
            {
                int row = warpK * 32 + (lane & 15);
                int col = ks * 16 + (lane >> 4) * 8;
                uint32_t o0 = (uint32_t)(row * ROWB + col * 2);
                LDSM_X4(ah0, aA + o0);
                LDSM_X4(ah1, aA + o0 + 16 * ROWB);
            }
            uint32_t brow = (uint32_t)((ks * 16 + (lane & 15)) * ROWB);
#pragma unroll
            for (int nt = 0; nt < 4; nt++) {
                uint32_t boff = brow + (uint32_t)((warpH * 32 + nt * 8) * 2);
                uint32_t bu2[2], bv2[2];
                LDSM_X2T(bu2, aBU + boff);
                mma16816(accU[0][nt], ah0, bu2);
                mma16816(accU[1][nt], ah1, bu2);
                LDSM_X2T(bv2, aBV + boff);
                mma16816(accV[0][nt], ah0, bv2);
                mma16816(accV[1][nt], ah1, bv2);
            }
        }

        // ---- epilogue (no gmem loads; Aq-fold, LN, exact gelu, Wo dot) ----
        float Rr[2][2], RMn[2][2];
        int krows[2][2];
#pragma unroll
        for (int mt = 0; mt < 2; mt++)
#pragma unroll
            for (int rp = 0; rp < 2; rp++) {
                int k = warpK * 32 + mt * 16 + (lane >> 2) + rp * 8;
                krows[mt][rp] = k;
                Rr[mt][rp] = sc->rr[t * 128 + k];
                RMn[mt][rp] = -sc->rmu[t * 128 + k];
            }
        float pr[2][2] = {{0.f, 0.f}, {0.f, 0.f}};
#pragma unroll
        for (int nt = 0; nt < 4; nt++) {
            int c0 = warpH * 32 + nt * 8 + 2 * (lane & 3);
            float2 AU = *(const float2*)&sc->AqU[c0];
            float2 AV = *(const float2*)&sc->AqV[c0];
            float2 GU = *(const float2*)&sc->Gu[c0];
            float2 BU = *(const float2*)&sc->Bu[c0];
            float2 GV = *(const float2*)&sc->Gv[c0];
            float2 BV = *(const float2*)&sc->Bv[c0];
            float2 WO = *(const float2*)&sc->Wo[c0];
#pragma unroll
            for (int mt = 0; mt < 2; mt++)
#pragma unroll
                for (int rp = 0; rp < 2; rp++) {
                    float R = Rr[mt][rp], RM = RMn[mt][rp];
                    float p = 0.f;
                    {
                        float au_ = accU[mt][nt][rp * 2 + 0] + AU.x;
                        float av_ = accV[mt][nt][rp * 2 + 0] + AV.x;
                        float uu = fmaf(R, au_, fmaf(RM, GU.x, BU.x));
                        float vv = fmaf(R, av_, fmaf(RM, GV.x, BV.x));
                        float gl = 0.5f * vv * (1.0f + erff(vv * 0.70710678118f));
                        p = fmaf(uu * gl, WO.x, p);
                    }
                    {
                        float au_ = accU[mt][nt][rp * 2 + 1] + AU.y;
                        float av_ = accV[mt][nt][rp * 2 + 1] + AV.y;
                        float uu = fmaf(R, au_, fmaf(RM, GU.y, BU.y));
                        float vv = fmaf(R, av_, fmaf(RM, GV.y, BV.y));
                        float gl = 0.5f * vv * (1.0f + erff(vv * 0.70710678118f));
                        p = fmaf(uu * gl, WO.y, p);
                    }
                    pr[mt][rp] += p;
                }
        }
#pragma unroll
        for (int mt = 0; mt < 2; mt++)
#pragma unroll
            for (int rp = 0; rp < 2; rp++) {
                float v = pr[mt][rp];
                v += __shfl_xor_sync(0xffffffffu, v, 1);
                v += __shfl_xor_sync(0xffffffffu, v, 2);
                if ((lane & 3) == 0) sc->pbuf[warpH][krows[mt][rp]] = v;
            }
        __syncthreads();
        if (tid < 128) {
            float r = sc->pbuf[0][tid] + sc->pbuf[1][tid] + sc->pbuf[2][tid]
                    + sc->pbuf[3][tid] + sc->bo;
            out[(size_t)bq * TK + t * 128 + tid] = r;
        }
        __syncthreads();
    }
}

// ---------------- launch ----------------
extern "C" void kernel_launch(void* const* d_in, const int* in_sizes, int n_in,
                              void* d_out, int out_size) {
    const float* Q    = (const float*)d_in[0];
    const float* K    = (const float*)d_in[1];
    const float* Wq   = (const float*)d_in[2];
    const float* Wk   = (const float*)d_in[3];
    const float* ln_g = (const float*)d_in[4];
    const float* ln_b = (const float*)d_in[5];
    const float* Wu   = (const float*)d_in[6];
    const float* bu   = (const float*)d_in[7];
    const float* Wv   = (const float*)d_in[8];
    const float* bv   = (const float*)d_in[9];
    const float* Wo   = (const float*)d_in[10];
    const float* bo   = (const float*)d_in[11];

    int B = in_sizes[0] / (TQ * QDIM);
    if (B < 1) B = 1;
    if (B > MAXB) B = MAXB;

    cudaFuncSetAttribute(k_main, cudaFuncAttributeMaxDynamicSharedMemorySize, SMEM_BYTES);

    k_wprep<<<HID, HID>>>(ln_g, Wu, Wv);
    k_gb<<<1, HID>>>(ln_g, ln_b, Wu, bu, Wv, bv);
    k_proj<<<2 * B * TQ / PROJ_ROWS, 128>>>(Q, K, Wq, Wk, B);
    k_kprep<<<B * TK, HID>>>(B);
    k_lin2<<<B * TQ / 16, 128>>>(B);
    k_main<<<B * TQ, 512, SMEM_BYTES>>>(Wo, bo, (float*)d_out);
}

// round 16
// speedup vs baseline: 4.1937x; 1.0100x over previous
#include <cuda_runtime.h>
#include <cuda_bf16.h>
#include <cuda_fp16.h>
#include <math.h>
#include <stdint.h>

#define HID   128
#define TQ    512
#define TK    512
#define QDIM  1024
#define MAXB  2
#define EPSF  1e-5f

#define PADJ   136                 // padded row length (fp16 elems) -> 272 B
#define ROWB   (PADJ * 2)          // 272
#define TILEB  (128 * ROWB)        // 34816

// ---------------- device scratch ----------------
__device__ __align__(16) float g_Qp[MAXB * TQ * HID];
__device__ __align__(16) float g_Kp[MAXB * TK * HID];
__device__ __align__(16) float g_W1u[HID * HID], g_W1v[HID * HID];
__device__ __align__(16) float g_W2u[HID * HID], g_W2v[HID * HID];
__device__ __align__(16) float g_W3u[HID * HID], g_W3v[HID * HID];
__device__ __align__(16) __half g_KpH[MAXB * TK * PADJ];
__device__ __align__(16) float g_AqU[MAXB * TQ * HID], g_AqV[MAXB * TQ * HID];
__device__ float g_Gu[HID], g_Bu[HID], g_Gv[HID], g_Bv[HID];

// ---------------- helpers ----------------
__device__ __forceinline__ uint32_t smem_u32(const void* p) {
    uint32_t a;
    asm("{ .reg .u64 t; cvta.to.shared.u64 t, %1; cvt.u32.u64 %0, t; }" : "=r"(a) : "l"(p));
    return a;
}
__device__ __forceinline__ uint32_t h2u(__half2 h) {
    union { __half2 b; uint32_t u; } x; x.b = h; return x.u;
}
#define LDSM_X4(r, a)                                                        \
    asm volatile("ldmatrix.sync.aligned.m8n8.x4.shared.b16 {%0,%1,%2,%3}, [%4];" \
        : "=r"((r)[0]), "=r"((r)[1]), "=r"((r)[2]), "=r"((r)[3]) : "r"(a))
#define LDSM_X2T(r, a)                                                       \
    asm volatile("ldmatrix.sync.aligned.m8n8.x2.trans.shared.b16 {%0,%1}, [%2];" \
        : "=r"((r)[0]), "=r"((r)[1]) : "r"(a))
#define CP_ASYNC16(dst, src) \
    asm volatile("cp.async.cg.shared.global [%0], [%1], 16;" :: "r"(dst), "l"(src))
#define CP_COMMIT() asm volatile("cp.async.commit_group;" ::: "memory")
#define CP_WAIT0()  asm volatile("cp.async.wait_group 0;" ::: "memory")

__device__ __forceinline__ void mma16816(float* d, const uint32_t* a, const uint32_t* b) {
    asm volatile("mma.sync.aligned.m16n8k16.row.col.f32.f16.f16.f32 "
        "{%0,%1,%2,%3}, {%4,%5,%6,%7}, {%8,%9}, {%0,%1,%2,%3};"
        : "+f"(d[0]), "+f"(d[1]), "+f"(d[2]), "+f"(d[3])
        : "r"(a[0]), "r"(a[1]), "r"(a[2]), "r"(a[3]), "r"(b[0]), "r"(b[1]));
}

// ---------------- prologue kernels ----------------
__global__ void k_wprep(const float* __restrict__ g,
                        const float* __restrict__ Wu, const float* __restrict__ Wv) {
    int j = blockIdx.x, h = threadIdx.x;
    float g0 = g[j], g1 = g[HID + j], g2 = g[2 * HID + j];
    g_W1u[j * HID + h] = g0 * Wu[j * HID + h];
    g_W1v[j * HID + h] = g0 * Wv[j * HID + h];
    g_W2u[j * HID + h] = g1 * Wu[(HID + j) * HID + h];
    g_W2v[j * HID + h] = g1 * Wv[(HID + j) * HID + h];
    g_W3u[j * HID + h] = g2 * Wu[(2 * HID + j) * HID + h];
    g_W3v[j * HID + h] = g2 * Wv[(2 * HID + j) * HID + h];
}

__global__ void k_gb(const float* __restrict__ g, const float* __restrict__ bln,
                     const float* __restrict__ Wu, const float* __restrict__ bu,
                     const float* __restrict__ Wv, const float* __restrict__ bv) {
    int h = threadIdx.x;
    float Gu = 0.f, Bu = 0.f, Gv = 0.f, Bv = 0.f;
    for (int c = 0; c < 3 * HID; c++) {
        float wu = Wu[c * HID + h], wv = Wv[c * HID + h];
        float gc = g[c], bc = bln[c];
        Gu = fmaf(gc, wu, Gu); Bu = fmaf(bc, wu, Bu);
        Gv = fmaf(gc, wv, Gv); Bv = fmaf(bc, wv, Bv);
    }
    g_Gu[h] = Gu; g_Bu[h] = Bu + bu[h];
    g_Gv[h] = Gv; g_Bv[h] = Bv + bv[h];
}

#define PROJ_ROWS 16
#define PROJ_DCHUNK 256
__global__ __launch_bounds__(128) void k_proj(const float* __restrict__ Q,
                                              const float* __restrict__ K,
                                              const float* __restrict__ Wq,
                                              const float* __restrict__ Wk, int B) {
    __shared__ __align__(16) float s[PROJ_ROWS][PROJ_DCHUNK];
    int nQ = B * TQ / PROJ_ROWS;
    bool isK = (int)blockIdx.x >= nQ;
    int blk = isK ? (blockIdx.x - nQ) : blockIdx.x;
    const float* X = isK ? K : Q;
    const float* W = isK ? Wk : Wq;
    int row0 = blk * PROJ_ROWS, h = threadIdx.x;
    float acc[PROJ_ROWS];
#pragma unroll
    for (int r = 0; r < PROJ_ROWS; r++) acc[r] = 0.f;
    for (int d0 = 0; d0 < QDIM; d0 += PROJ_DCHUNK) {
        for (int i = threadIdx.x; i < PROJ_ROWS * (PROJ_DCHUNK / 4); i += 128) {
            int r = i / (PROJ_DCHUNK / 4), c4 = i % (PROJ_DCHUNK / 4);
            *(float4*)&s[r][c4 * 4] = *(const float4*)&X[(size_t)(row0 + r) * QDIM + d0 + c4 * 4];
        }
        __syncthreads();
        for (int dd = 0; dd < PROJ_DCHUNK; dd += 4) {
            float w0 = W[(d0 + dd + 0) * HID + h], w1 = W[(d0 + dd + 1) * HID + h];
            float w2 = W[(d0 + dd + 2) * HID + h], w3 = W[(d0 + dd + 3) * HID + h];
#pragma unroll
            for (int r = 0; r < PROJ_ROWS; r++) {
                float4 sv = *(const float4*)&s[r][dd];
                acc[r] = fmaf(sv.x, w0, acc[r]); acc[r] = fmaf(sv.y, w1, acc[r]);
                acc[r] = fmaf(sv.z, w2, acc[r]); acc[r] = fmaf(sv.w, w3, acc[r]);
            }
        }
        __syncthreads();
    }
#pragma unroll
    for (int r = 0; r < PROJ_ROWS; r++) {
        int grow = row0 + r;
        if (isK) g_Kp[(size_t)grow * HID + h] = acc[r];
        else     g_Qp[(size_t)grow * HID + h] = acc[r];
    }
}

// fp16 image of Kp, padded rows (LDSM-ready)
__global__ void k_kprep(int B) {
    int k = blockIdx.x;       // over B*TK
    int h = threadIdx.x;      // 0..127
    g_KpH[(size_t)k * PADJ + h] = __float2half_rn(g_Kp[(size_t)k * HID + h]);
}

// Aq = Qp@W1 (u,v)
__global__ __launch_bounds__(128) void k_lin2(int B) {
    __shared__ __align__(16) float s[16][HID];
    int row0 = blockIdx.x * 16, h = threadIdx.x;
    for (int i = threadIdx.x; i < 16 * 32; i += 128) {
        int r = i >> 5, c = i & 31;
        *(float4*)&s[r][c * 4] = *(const float4*)&g_Qp[(size_t)(row0 + r) * HID + c * 4];
    }
    __syncthreads();
    float au[16], av[16];
#pragma unroll
    for (int r = 0; r < 16; r++) { au[r] = 0.f; av[r] = 0.f; }
    for (int j = 0; j < HID; j++) {
        float wa = g_W1u[j * HID + h], wb = g_W1v[j * HID + h];
#pragma unroll
        for (int r = 0; r < 16; r++) {
            float kv = s[r][j];
            au[r] = fmaf(kv, wa, au[r]); av[r] = fmaf(kv, wb, av[r]);
        }
    }
#pragma unroll
    for (int r = 0; r < 16; r++) {
        g_AqU[(size_t)(row0 + r) * HID + h] = au[r];
        g_AqV[(size_t)(row0 + r) * HID + h] = av[r];
    }
}

// ---------------- main fused kernel ----------------
struct __align__(16) ScalS {
    float qrow[HID];
    float AqU[HID], AqV[HID];
    float Gu[HID], Bu[HID], Gv[HID], Bv[HID], Wo[HID];
    float rr[TK], rmu[TK];
    float pbuf[4][4][HID];    // [tile][warpH][k]
    float red1[4], red2[4];
    float sq, sq2, bo, pad;
};
#define OFF_BU  0
#define OFF_BV  (1 * TILEB)
#define OFF_A   (2 * TILEB)   // 4 A tiles, contiguous
#define OFF_SCAL (6 * TILEB)
#define SMEM_BYTES (OFF_SCAL + (int)sizeof(ScalS) + 128)

__global__ __launch_bounds__(512, 1) void k_main(const float* __restrict__ Wo_g,
                                                 const float* __restrict__ bo_g,
                                                 float* __restrict__ out) {
    extern __shared__ char smraw[];
    uint32_t sb = smem_u32(smraw);
    uint32_t base = (sb + 127u) & ~127u;
    char* cbase = smraw + (base - sb);
    ScalS* sc = (ScalS*)(cbase + OFF_SCAL);

    const int tid = threadIdx.x;
    const int wrp = tid >> 5, lane = tid & 31;
    const int warpK = wrp & 3, warpH = wrp >> 2;
    const int bq = blockIdx.x, b = bq / TQ;

    const uint32_t aBU = base + OFF_BU, aBV = base + OFF_BV;

    // prefetch ALL 4 A tiles (Kp fp16 image for this batch, 139 KB, L2-resident)
    {
        const char* srcH = (const char*)&g_KpH[(size_t)(b * TK) * PADJ];
        uint32_t dH = base + OFF_A;
        for (int i = tid; i < 4 * TILEB / 16; i += 512)
            CP_ASYNC16(dH + i * 16, srcH + i * 16);
        CP_COMMIT();
    }

    if (tid < HID) {
        sc->qrow[tid] = g_Qp[(size_t)bq * HID + tid];
        sc->AqU[tid] = g_AqU[(size_t)bq * HID + tid];
        sc->AqV[tid] = g_AqV[(size_t)bq * HID + tid];
        sc->Gu[tid] = g_Gu[tid]; sc->Bu[tid] = g_Bu[tid];
        sc->Gv[tid] = g_Gv[tid]; sc->Bv[tid] = g_Bv[tid];
        sc->Wo[tid] = Wo_g[tid];
    }
    if (tid == 0) sc->bo = bo_g[0];
    __syncthreads();

    if (tid < 128) {
        float q = sc->qrow[tid];
        float s = q, s2 = q * q;
#pragma unroll
        for (int o = 16; o; o >>= 1) {
            s  += __shfl_xor_sync(0xffffffffu, s,  o);
            s2 += __shfl_xor_sync(0xffffffffu, s2, o);
        }
        if (lane == 0) { sc->red1[wrp] = s; sc->red2[wrp] = s2; }
    }
    __syncthreads();
    if (tid == 0) {
        sc->sq  = sc->red1[0] + sc->red1[1] + sc->red1[2] + sc->red1[3];
        sc->sq2 = sc->red2[0] + sc->red2[1] + sc->red2[2] + sc->red2[3];
    }
    __syncthreads();
    const float sqv = sc->sq, sq2v = sc->sq2, inv384 = 1.0f / 384.0f;

    // ---- build B_q = diag(q)*W3 + W2 (u,v) as single fp16 images ----
    for (int i = tid; i < 4096; i += 512) {
        int j = i >> 5, c4 = (i & 31) << 2;
        float qj = sc->qrow[j];
        float4 w3u = *(const float4*)&g_W3u[j * HID + c4];
        float4 w2u = *(const float4*)&g_W2u[j * HID + c4];
        float4 w3v = *(const float4*)&g_W3v[j * HID + c4];
        float4 w2v = *(const float4*)&g_W2v[j * HID + c4];
        __half2 U0 = __floats2half2_rn(fmaf(qj, w3u.x, w2u.x), fmaf(qj, w3u.y, w2u.y));
        __half2 U1 = __floats2half2_rn(fmaf(qj, w3u.z, w2u.z), fmaf(qj, w3u.w, w2u.w));
        __half2 V0 = __floats2half2_rn(fmaf(qj, w3v.x, w2v.x), fmaf(qj, w3v.y, w2v.y));
        __half2 V1 = __floats2half2_rn(fmaf(qj, w3v.z, w2v.z), fmaf(qj, w3v.w, w2v.w));
        uint32_t ad = (uint32_t)(j * ROWB + c4 * 2);
        uint2 t0;
        t0.x = h2u(U0); t0.y = h2u(U1); *(uint2*)(cbase + OFF_BU + ad) = t0;
        t0.x = h2u(V0); t0.y = h2u(V1); *(uint2*)(cbase + OFF_BV + ad) = t0;
    }

    // ---- per-k LN stats for all 512 k (exact fp32) ----
    {
        int k = tid;
        const float* kr = &g_Kp[((size_t)(b * TK + k)) * HID];
        float dqk = 0.f, d22 = 0.f, skv = 0.f, sk2v = 0.f;
#pragma unroll 4
        for (int j = 0; j < HID; j += 4) {
            float4 v = *(const float4*)&kr[j];
            float4 q = *(const float4*)&sc->qrow[j];
            float a0 = q.x * v.x, a1 = q.y * v.y, a2 = q.z * v.z, a3 = q.w * v.w;
            skv += v.x + v.y + v.z + v.w;
            sk2v = fmaf(v.x, v.x, sk2v); sk2v = fmaf(v.y, v.y, sk2v);
            sk2v = fmaf(v.z, v.z, sk2v); sk2v = fmaf(v.w, v.w, sk2v);
            dqk += a0 + a1 + a2 + a3;
            d22 = fmaf(a0, a0, d22); d22 = fmaf(a1, a1, d22);
            d22 = fmaf(a2, a2, d22); d22 = fmaf(a3, a3, d22);
        }
        float mu = (sqv + skv + dqk) * inv384;
        float ms = (sq2v + sk2v + d22) * inv384;
        float R0 = rsqrtf(ms - mu * mu + EPSF);
        sc->rr[k]  = R0;
        sc->rmu[k] = R0 * mu;
    }

    CP_WAIT0();
    __syncthreads();    // the ONLY barrier before the mainloop

    // ================= barrier-free mainloop =================
    for (int t = 0; t < 4; t++) {
        const uint32_t aA = base + OFF_A + (uint32_t)(t * TILEB);

        float accU[2][4][4], accV[2][4][4];
#pragma unroll
        for (int mt = 0; mt < 2; mt++)
#pragma unroll
            for (int nt = 0; nt < 4; nt++)
#pragma unroll
                for (int d = 0; d < 4; d++) { accU[mt][nt][d] = 0.f; accV[mt][nt][d] = 0.f; }

#pragma unroll
        for (int ks = 0; ks < 8; ks++) {
            uint32_t ah0[4], ah1[4];
            {
                int row = warpK * 32 + (lane & 15);
                int col = ks * 16 + (lane >> 4) * 8;
                uint32_t o0 = (uint32_t)(row * ROWB + col * 2);
                LDSM_X4(ah0, aA + o0);
                LDSM_X4(ah1, aA + o0 + 16 * ROWB);
            }
            uint32_t brow = (uint32_t)((ks * 16 + (lane & 15)) * ROWB);
#pragma unroll
            for (int nt = 0; nt < 4; nt++) {
                uint32_t boff = brow + (uint32_t)((warpH * 32 + nt * 8) * 2);
                uint32_t bu2[2], bv2[2];
                LDSM_X2T(bu2, aBU + boff);
                mma16816(accU[0][nt], ah0, bu2);
                mma16816(accU[1][nt], ah1, bu2);
                LDSM_X2T(bv2, aBV + boff);
                mma16816(accV[0][nt], ah0, bv2);
                mma16816(accV[1][nt], ah1, bv2);
            }
        }

        // ---- epilogue (register-resident; pbuf write-once, no sync) ----
        float Rr[2][2], RMn[2][2];
        int krows[2][2];
#pragma unroll
        for (int mt = 0; mt < 2; mt++)
#pragma unroll
            for (int rp = 0; rp < 2; rp++) {
                int k = warpK * 32 + mt * 16 + (lane >> 2) + rp * 8;
                krows[mt][rp] = k;
                Rr[mt][rp] = sc->rr[t * 128 + k];
                RMn[mt][rp] = -sc->rmu[t * 128 + k];
            }
        float pr[2][2] = {{0.f, 0.f}, {0.f, 0.f}};
#pragma unroll
        for (int nt = 0; nt < 4; nt++) {
            int c0 = warpH * 32 + nt * 8 + 2 * (lane & 3);
            float2 AU = *(const float2*)&sc->AqU[c0];
            float2 AV = *(const float2*)&sc->AqV[c0];
            float2 GU = *(const float2*)&sc->Gu[c0];
            float2 BU = *(const float2*)&sc->Bu[c0];
            float2 GV = *(const float2*)&sc->Gv[c0];
            float2 BV = *(const float2*)&sc->Bv[c0];
            float2 WO = *(const float2*)&sc->Wo[c0];
#pragma unroll
            for (int mt = 0; mt < 2; mt++)
#pragma unroll
                for (int rp = 0; rp < 2; rp++) {
                    float R = Rr[mt][rp], RM = RMn[mt][rp];
                    float p = 0.f;
                    {
                        float au_ = accU[mt][nt][rp * 2 + 0] + AU.x;
                        float av_ = accV[mt][nt][rp * 2 + 0] + AV.x;
                        float uu = fmaf(R, au_, fmaf(RM, GU.x, BU.x));
                        float vv = fmaf(R, av_, fmaf(RM, GV.x, BV.x));
                        float gl = 0.5f * vv * (1.0f + erff(vv * 0.70710678118f));
                        p = fmaf(uu * gl, WO.x, p);
                    }
                    {
                        float au_ = accU[mt][nt][rp * 2 + 1] + AU.y;
                        float av_ = accV[mt][nt][rp * 2 + 1] + AV.y;
                        float uu = fmaf(R, au_, fmaf(RM, GU.y, BU.y));
                        float vv = fmaf(R, av_, fmaf(RM, GV.y, BV.y));
                        float gl = 0.5f * vv * (1.0f + erff(vv * 0.70710678118f));
                        p = fmaf(uu * gl, WO.y, p);
                    }
                    pr[mt][rp] += p;
                }
        }
#pragma unroll
        for (int mt = 0; mt < 2; mt++)
#pragma unroll
            for (int rp = 0; rp < 2; rp++) {
                float v = pr[mt][rp];
                v += __shfl_xor_sync(0xffffffffu, v, 1);
                v += __shfl_xor_sync(0xffffffffu, v, 2);
                if ((lane & 3) == 0) sc->pbuf[t][warpH][krows[mt][rp]] = v;
            }
    }

    __syncthreads();   // single final barrier
    {
        int tt = tid >> 7, kk = tid & 127;
        float r = sc->pbuf[tt][0][kk] + sc->pbuf[tt][1][kk]
                + sc->pbuf[tt][2][kk] + sc->pbuf[tt][3][kk] + sc->bo;
        out[(size_t)bq * TK + tt * 128 + kk] = r;
    }
}

// ---------------- launch ----------------
extern "C" void kernel_launch(void* const* d_in, const int* in_sizes, int n_in,
                              void* d_out, int out_size) {
    const float* Q    = (const float*)d_in[0];
    const float* K    = (const float*)d_in[1];
    const float* Wq   = (const float*)d_in[2];
    const float* Wk   = (const float*)d_in[3];
    const float* ln_g = (const float*)d_in[4];
    const float* ln_b = (const float*)d_in[5];
    const float* Wu   = (const float*)d_in[6];
    const float* bu   = (const float*)d_in[7];
    const float* Wv   = (const float*)d_in[8];
    const float* bv   = (const float*)d_in[9];
    const float* Wo   = (const float*)d_in[10];
    const float* bo   = (const float*)d_in[11];

    int B = in_sizes[0] / (TQ * QDIM);
    if (B < 1) B = 1;
    if (B > MAXB) B = MAXB;

    cudaFuncSetAttribute(k_main, cudaFuncAttributeMaxDynamicSharedMemorySize, SMEM_BYTES);

    k_wprep<<<HID, HID>>>(ln_g, Wu, Wv);
    k_gb<<<1, HID>>>(ln_g, ln_b, Wu, bu, Wv, bv);
    k_proj<<<2 * B * TQ / PROJ_ROWS, 128>>>(Q, K, Wq, Wk, B);
    k_kprep<<<B * TK, HID>>>(B);
    k_lin2<<<B * TQ / 16, 128>>>(B);
    k_main<<<B * TQ, 512, SMEM_BYTES>>>(Wo, bo, (float*)d_out);
}